// round 15
// baseline (speedup 1.0000x reference)
#include <cuda_runtime.h>
#include <cuda_fp16.h>
#include <math.h>
#include <stdint.h>

// Problem constants: B=2, T=4096, d_model=1024, H=16, d_head=64, m=64
#define T_SEQ 4096
#define DMODEL 1024
#define NBH    32      // B*H
#define NROWS  8192    // B*T
#define NSWEEP 12

// ---------------- device scratch (no runtime allocation allowed) ----------------
__device__ __align__(16) float g_QKV[3 * NROWS * DMODEL];   // Q | K | V
__device__ __align__(16) float g_A[NBH * T_SEQ * 64];       // A_hat
__device__ __align__(16) float g_S[NBH * T_SEQ * 64];       // exp(B scores)
__device__ __align__(16) float g_xlm[128 * DMODEL];         // segment means of x
__device__ __align__(16) float g_Qlm[NBH * 64 * 64];
__device__ __align__(16) float g_Klm[NBH * 64 * 64];
__device__ __align__(16) float g_CBV[NBH * 64 * 64];
__device__ __align__(16) float g_BVpart[NBH * 8 * 64 * 64];
__device__ float g_csump[NBH * 8 * 64];
// Jacobi SVD intermediates (COLUMN-major: out[c*64+r] = M[r][c])
__device__ __align__(16) float g_Gm[NBH * 64 * 64];
__device__ __align__(16) float g_Vm[NBH * 64 * 64];
__device__ float g_wv[NBH * 64];
// fp16 splits
__device__ __align__(16) __half g_xh[NROWS * DMODEL];
__device__ __align__(16) __half g_xl[NROWS * DMODEL];
__device__ __align__(16) __half g_wh[4][DMODEL * DMODEL];
__device__ __align__(16) __half g_wl[4][DMODEL * DMODEL];
__device__ __align__(16) __half g_ah[NROWS * DMODEL];
__device__ __align__(16) __half g_al[NROWS * DMODEL];

// =====================  helpers  =====================
__device__ __forceinline__ uint32_t smem_u32(const void* p) {
    return (uint32_t)__cvta_generic_to_shared(p);
}
__device__ __forceinline__ void cp16(uint32_t dst, const void* src) {
    asm volatile("cp.async.cg.shared.global [%0], [%1], 16;" :: "r"(dst), "l"(src));
}
__device__ __forceinline__ void ldsm_x4(uint32_t* r, uint32_t addr) {
    asm volatile("ldmatrix.sync.aligned.m8n8.x4.shared.b16 {%0,%1,%2,%3}, [%4];"
        : "=r"(r[0]), "=r"(r[1]), "=r"(r[2]), "=r"(r[3]) : "r"(addr));
}
#define MMA16816F(d, a, b) \
    asm volatile("mma.sync.aligned.m16n8k16.row.col.f32.f16.f16.f32 " \
        "{%0,%1,%2,%3},{%4,%5,%6,%7},{%8,%9},{%0,%1,%2,%3};" \
        : "+f"((d)[0]), "+f"((d)[1]), "+f"((d)[2]), "+f"((d)[3]) \
        : "r"((a)[0]), "r"((a)[1]), "r"((a)[2]), "r"((a)[3]), \
          "r"((b)[0]), "r"((b)[1]))

// ---------------------------------------------------------------------------
// One flat split kernel: weights (hi+lo) then x (hi+lo).
// ---------------------------------------------------------------------------
__device__ __forceinline__ void split4(float4 v, __half2* hi, __half2* lo, size_t i2) {
    __half h0 = __float2half(v.x), h1 = __float2half(v.y);
    __half h2 = __float2half(v.z), h3 = __float2half(v.w);
    __half2 H0, H1, L0, L1;
    H0.x = h0; H0.y = h1; H1.x = h2; H1.y = h3;
    L0.x = __float2half(v.x - __half2float(h0));
    L0.y = __float2half(v.y - __half2float(h1));
    L1.x = __float2half(v.z - __half2float(h2));
    L1.y = __float2half(v.w - __half2float(h3));
    hi[i2] = H0; hi[i2+1] = H1;
    lo[i2] = L0; lo[i2+1] = L1;
}

__global__ void split_all_kernel(
    const float4* __restrict__ x,
    const float4* __restrict__ W0, const float4* __restrict__ W1,
    const float4* __restrict__ W2, const float4* __restrict__ W3,
    __half2* __restrict__ xh2, __half2* __restrict__ xl2,
    __half2* __restrict__ wh2, __half2* __restrict__ wl2)
{
    int idx = blockIdx.x * 256 + threadIdx.x;
    if (idx < 4 * 262144) {
        int w = idx >> 18;
        int i = idx & 262143;
        const float4* src = (w == 0) ? W0 : (w == 1) ? W1 : (w == 2) ? W2 : W3;
        split4(src[i], wh2, wl2, (size_t)w * 524288 + 2 * (size_t)i);
    } else {
        int j = idx - 4 * 262144;
        split4(x[j], xh2, xl2, 2 * (size_t)j);
    }
}

// ---------------------------------------------------------------------------
// xlm: segment means of x.  xlm[m][k] = mean over 64 t of x[b*4096+seg*64+t][k]
// where m = b*64+seg.  grid 128, 256 threads.
// ---------------------------------------------------------------------------
__global__ void xlm_kernel(const float* __restrict__ x, float* __restrict__ xlm)
{
    int m = blockIdx.x;            // 0..127
    int b = m >> 6, seg = m & 63;
    const float* base = x + ((size_t)b * T_SEQ + seg * 64) * DMODEL;
    int tid = threadIdx.x;
#pragma unroll
    for (int cc = 0; cc < 4; cc++) {
        int c = tid + cc * 256;
        float s = 0.f;
#pragma unroll 8
        for (int r = 0; r < 64; r++) s += base[(size_t)r * DMODEL + c];
        xlm[(size_t)m * DMODEL + c] = s * 0.015625f;
    }
}

// ---------------------------------------------------------------------------
// lmgemm: Qlm/Klm = xlm @ W^T  (fp32 SIMT, exact — feeds the pinv path).
// grid (16 n-tiles of 64, 2 weights), 256 threads, 4x8 micro per thread.
// out[(b*16+h)*4096 + mi*64 + d] where row m=b*64+mi, col n=h*64+d.
// ---------------------------------------------------------------------------
__global__ __launch_bounds__(256) void lmgemm_kernel(
    const float* __restrict__ xlm,
    const float* __restrict__ Wq, const float* __restrict__ Wk,
    float* __restrict__ Qlm, float* __restrict__ Klm)
{
    const float* W = blockIdx.y ? Wk : Wq;
    float* out = blockIdx.y ? Klm : Qlm;
    int n0 = blockIdx.x * 64;
    __shared__ float xs[16][132];   // [k][m]
    __shared__ float ws[16][68];    // [k][n]
    int tid = threadIdx.x;
    int ti = tid >> 3;   // 0..31 (4 rows each)
    int tj = tid & 7;    // 0..7  (8 cols each)
    float acc[4][8] = {};
    for (int k0 = 0; k0 < DMODEL; k0 += 16) {
        __syncthreads();
        for (int i = tid; i < 2048; i += 256) {
            int kk = i >> 7, m = i & 127;
            xs[kk][m] = xlm[(size_t)m * DMODEL + k0 + kk];
        }
        for (int i = tid; i < 1024; i += 256) {
            int kk = i >> 6, n = i & 63;
            ws[kk][n] = W[(size_t)(n0 + n) * DMODEL + k0 + kk];
        }
        __syncthreads();
#pragma unroll
        for (int kk = 0; kk < 16; kk++) {
            float a[4], b[8];
#pragma unroll
            for (int x2 = 0; x2 < 4; x2++) a[x2] = xs[kk][ti*4 + x2];
#pragma unroll
            for (int y = 0; y < 8; y++) b[y] = ws[kk][tj*8 + y];
#pragma unroll
            for (int x2 = 0; x2 < 4; x2++)
#pragma unroll
                for (int y = 0; y < 8; y++)
                    acc[x2][y] = fmaf(a[x2], b[y], acc[x2][y]);
        }
    }
#pragma unroll
    for (int x2 = 0; x2 < 4; x2++) {
        int m = ti*4 + x2;
        int b = m >> 6, mi = m & 63;
#pragma unroll
        for (int y = 0; y < 8; y++) {
            int n = n0 + tj*8 + y;
            int h = n >> 6, d = n & 63;
            out[((size_t)(b*16 + h) * 64 + mi) * 64 + d] = acc[x2][y];
        }
    }
}

// ---------------------------------------------------------------------------
// 3-term NT GEMM tile body: C = Ah*Bh + Ah*Bl + Al*Bh (fp32 acc).
// 128x128 tile, K-chunks of 32, 2-stage cp.async, 80B pitch.
// ---------------------------------------------------------------------------
#define GM_ROWB  80
#define GM_TILE  (128 * GM_ROWB)      // 10240
#define G3_STAGE (4 * GM_TILE)        // 40960
#define G3_SMEM  (2 * G3_STAGE)       // 81920

__device__ void dev_gemm3(char* smem, int m0, int n0,
    const __half* __restrict__ Ahi, const __half* __restrict__ Alo,
    const __half* __restrict__ Bhi, const __half* __restrict__ Blo,
    float* __restrict__ C, int N, int K)
{
    const uint32_t sb = smem_u32(smem);
    const int tid = threadIdx.x;
    const int wid = tid >> 5, lane = tid & 31;
    const int wr = (wid & 3) * 32;
    const int wc = (wid >> 2) * 64;
    const int lrow = tid >> 2;
    const int lseg = tid & 3;

    const int nchunks = K >> 5;

    auto load_stage = [&](int s, int kc) {
        uint32_t st = sb + s * G3_STAGE;
#pragma unroll
        for (int i = 0; i < 2; i++) {
            int row = lrow + i * 64;
            uint32_t off = row * GM_ROWB + lseg * 16;
            cp16(st +             off, Ahi + (size_t)(m0 + row) * K + kc + lseg * 8);
            cp16(st + GM_TILE   + off, Alo + (size_t)(m0 + row) * K + kc + lseg * 8);
            cp16(st + 2*GM_TILE + off, Bhi + (size_t)(n0 + row) * K + kc + lseg * 8);
            cp16(st + 3*GM_TILE + off, Blo + (size_t)(n0 + row) * K + kc + lseg * 8);
        }
        asm volatile("cp.async.commit_group;" ::: "memory");
    };

    load_stage(0, 0);
    load_stage(1, 32);

    float accF[2][8][4];
#pragma unroll
    for (int mt = 0; mt < 2; mt++)
#pragma unroll
        for (int nt = 0; nt < 8; nt++)
#pragma unroll
            for (int q = 0; q < 4; q++) accF[mt][nt][q] = 0.f;

    const uint32_t aBase = (uint32_t)(wr + (lane & 15)) * GM_ROWB + (uint32_t)(lane >> 4) * 16;
    const uint32_t bBase = (uint32_t)(wc + (lane & 7) + ((lane >> 4) * 8)) * GM_ROWB
                         + (uint32_t)((lane >> 3) & 1) * 16;

    const int fr = lane >> 2;
    const int fc = (lane & 3) * 2;

    for (int c = 0; c < nchunks; c++) {
        int s = c & 1;
        asm volatile("cp.async.wait_group 1;" ::: "memory");
        __syncthreads();
        uint32_t st  = sb + s * G3_STAGE;
        uint32_t tAH = st;
        uint32_t tAL = st + GM_TILE;
        uint32_t tBH = st + 2*GM_TILE;
        uint32_t tBL = st + 3*GM_TILE;

#pragma unroll
        for (int k16 = 0; k16 < 2; k16++) {
            uint32_t kb = k16 * 32;
            uint32_t aH[2][4], aL[2][4];
#pragma unroll
            for (int mt = 0; mt < 2; mt++) {
                uint32_t ao = aBase + mt * 16 * GM_ROWB + kb;
                ldsm_x4(aH[mt], tAH + ao);
                ldsm_x4(aL[mt], tAL + ao);
            }
            uint32_t bH[8][2], bL[8][2];
#pragma unroll
            for (int p = 0; p < 4; p++) {
                uint32_t bo = bBase + p * 16 * GM_ROWB + kb;
                uint32_t tH[4], tL[4];
                ldsm_x4(tH, tBH + bo);
                ldsm_x4(tL, tBL + bo);
                bH[2*p][0] = tH[0]; bH[2*p][1] = tH[1];
                bH[2*p+1][0] = tH[2]; bH[2*p+1][1] = tH[3];
                bL[2*p][0] = tL[0]; bL[2*p][1] = tL[1];
                bL[2*p+1][0] = tL[2]; bL[2*p+1][1] = tL[3];
            }
#pragma unroll
            for (int mt = 0; mt < 2; mt++)
#pragma unroll
                for (int nt = 0; nt < 8; nt++)
                    MMA16816F(accF[mt][nt], aH[mt], bH[nt]);
#pragma unroll
            for (int mt = 0; mt < 2; mt++)
#pragma unroll
                for (int nt = 0; nt < 8; nt++)
                    MMA16816F(accF[mt][nt], aH[mt], bL[nt]);
#pragma unroll
            for (int mt = 0; mt < 2; mt++)
#pragma unroll
                for (int nt = 0; nt < 8; nt++)
                    MMA16816F(accF[mt][nt], aL[mt], bH[nt]);
        }
        __syncthreads();
        if (c + 2 < nchunks) {
            load_stage(s, (c + 2) * 32);
        } else {
            asm volatile("cp.async.commit_group;" ::: "memory");
        }
    }

#pragma unroll
    for (int mt = 0; mt < 2; mt++) {
#pragma unroll
        for (int nt = 0; nt < 8; nt++) {
            int row = m0 + wr + mt*16 + fr;
            int col = n0 + wc + nt*8 + fc;
            *(float2*)(C + (size_t)row * N + col) =
                make_float2(accF[mt][nt][0], accF[mt][nt][1]);
            *(float2*)(C + (size_t)(row + 8) * N + col) =
                make_float2(accF[mt][nt][2], accF[mt][nt][3]);
        }
    }
}

// standalone gemm3 kernel (out projection)
__global__ __launch_bounds__(256, 2) void gemm3_kernel(
    const __half* __restrict__ Ahi, const __half* __restrict__ Alo,
    const __half* __restrict__ Bhi, const __half* __restrict__ Blo,
    float* __restrict__ C, int N, int K)
{
    extern __shared__ __align__(128) char smem[];
    dev_gemm3(smem, blockIdx.y * 128, blockIdx.x * 128,
              Ahi, Alo, Bhi, Blo, C, N, K);
}

// ---------------------------------------------------------------------------
// Jacobi SVD body. Column-major pitch-68, float4 ops, tracked norms,
// fast-math on angle path only; sigma/cutoff/softmax exact.
// ---------------------------------------------------------------------------
#define JP 68

__device__ void dev_jacobi(char* smemc, int bh,
    const float* __restrict__ Qlm, const float* __restrict__ Klm,
    float* __restrict__ Gout, float* __restrict__ Vout, float* __restrict__ wv)
{
    float* sp = (float*)smemc;
    float* Gt   = sp;             // 64*68
    float* Vt   = sp + 4352;      // 64*68
    float* cn   = sp + 8704;      // 64
    float* svec = sp + 8768;      // 64
    int tid = threadIdx.x;
    int ti = tid >> 4, tj = tid & 15;

    for (int i = tid; i < 4096; i += 256) {
        int r = i >> 6, c = i & 63;
        Gt[r*JP + c] = Qlm[(size_t)bh*4096 + i];
        Vt[r*JP + c] = Klm[(size_t)bh*4096 + i];
    }
    __syncthreads();

    float cacc[4][4] = {};
    for (int d = 0; d < 64; d++) {
        float qa[4], kb[4];
#pragma unroll
        for (int x = 0; x < 4; x++) qa[x] = Gt[(ti*4+x)*JP + d];
#pragma unroll
        for (int y = 0; y < 4; y++) kb[y] = Vt[(tj*4+y)*JP + d];
#pragma unroll
        for (int x = 0; x < 4; x++)
#pragma unroll
            for (int y = 0; y < 4; y++)
                cacc[x][y] = fmaf(qa[x], kb[y], cacc[x][y]);
    }
    __syncthreads();
#pragma unroll
    for (int x = 0; x < 4; x++)
#pragma unroll
        for (int y = 0; y < 4; y++)
            Vt[(ti*4+x)*JP + tj*4+y] = cacc[x][y] * 0.125f;
    __syncthreads();

    // row softmax (exact)
    if (tid < 64) {
        float mx = -INFINITY;
        for (int c = 0; c < 64; c++) mx = fmaxf(mx, Vt[tid*JP + c]);
        float z = 0.f;
        for (int c = 0; c < 64; c++) {
            float e = expf(Vt[tid*JP + c] - mx);
            Vt[tid*JP + c] = e; z += e;
        }
        float inv = 1.f / z;
        for (int c = 0; c < 64; c++) Vt[tid*JP + c] *= inv;
    }
    __syncthreads();

    for (int i = tid; i < 4096; i += 256) {
        int r = i >> 6, c = i & 63;
        Gt[c*JP + r] = Vt[r*JP + c];
    }
    __syncthreads();
    for (int i = tid; i < 4096; i += 256) {
        int r = i >> 6, c = i & 63;
        Vt[c*JP + r] = (r == c) ? 1.f : 0.f;
    }
    __syncthreads();

    {
        int p = tid >> 3, lane = tid & 7;
        for (int sw = 0; sw < NSWEEP; sw++) {
            if (tid < 64) {
                const float* col = Gt + tid*JP;
                float s = 0.f;
#pragma unroll
                for (int k4 = 0; k4 < 16; k4++) {
                    float4 v = *(const float4*)(col + 4*k4);
                    s = fmaf(v.x, v.x, s); s = fmaf(v.y, v.y, s);
                    s = fmaf(v.z, v.z, s); s = fmaf(v.w, v.w, s);
                }
                cn[tid] = s;
            }
            __syncthreads();

            for (int r = 0; r < 63; r++) {
                int ci, cj;
                if (p == 0) { ci = 63; cj = r; }
                else { ci = (r + p) % 63; cj = (r - p + 63) % 63; }
                float* gi = Gt + ci*JP + 8*lane;
                float* gj = Gt + cj*JP + 8*lane;
                float4 a0 = *(float4*)(gi);
                float4 a1 = *(float4*)(gi + 4);
                float4 b0 = *(float4*)(gj);
                float4 b1 = *(float4*)(gj + 4);
                float gg = a0.x*b0.x + a0.y*b0.y + a0.z*b0.z + a0.w*b0.w
                         + a1.x*b1.x + a1.y*b1.y + a1.z*b1.z + a1.w*b1.w;
#pragma unroll
                for (int o = 4; o > 0; o >>= 1)
                    gg += __shfl_xor_sync(0xffffffffu, gg, o);
                float aa = cn[ci], bb = cn[cj];
                float c_ = 1.f, s_ = 0.f;
                if (fabsf(gg) > 1e-30f) {
                    float zeta = __fdividef(bb - aa, 2.0f * gg);
                    float t = copysignf(
                        __fdividef(1.0f, fabsf(zeta) + sqrtf(fmaf(zeta, zeta, 1.0f))),
                        zeta);
                    c_ = rsqrtf(fmaf(t, t, 1.0f));
                    s_ = c_ * t;
                }
                if (s_ != 0.f) {
                    float4 n0, n1, m0, m1;
                    n0.x = c_*a0.x - s_*b0.x; n0.y = c_*a0.y - s_*b0.y;
                    n0.z = c_*a0.z - s_*b0.z; n0.w = c_*a0.w - s_*b0.w;
                    n1.x = c_*a1.x - s_*b1.x; n1.y = c_*a1.y - s_*b1.y;
                    n1.z = c_*a1.z - s_*b1.z; n1.w = c_*a1.w - s_*b1.w;
                    m0.x = s_*a0.x + c_*b0.x; m0.y = s_*a0.y + c_*b0.y;
                    m0.z = s_*a0.z + c_*b0.z; m0.w = s_*a0.w + c_*b0.w;
                    m1.x = s_*a1.x + c_*b1.x; m1.y = s_*a1.y + c_*b1.y;
                    m1.z = s_*a1.z + c_*b1.z; m1.w = s_*a1.w + c_*b1.w;
                    *(float4*)(gi)     = n0; *(float4*)(gi + 4) = n1;
                    *(float4*)(gj)     = m0; *(float4*)(gj + 4) = m1;
                    float* vi = Vt + ci*JP + 8*lane;
                    float* vj = Vt + cj*JP + 8*lane;
                    float4 p0 = *(float4*)(vi), p1 = *(float4*)(vi + 4);
                    float4 q0 = *(float4*)(vj), q1 = *(float4*)(vj + 4);
                    float4 u0, u1, w0, w1;
                    u0.x = c_*p0.x - s_*q0.x; u0.y = c_*p0.y - s_*q0.y;
                    u0.z = c_*p0.z - s_*q0.z; u0.w = c_*p0.w - s_*q0.w;
                    u1.x = c_*p1.x - s_*q1.x; u1.y = c_*p1.y - s_*q1.y;
                    u1.z = c_*p1.z - s_*q1.z; u1.w = c_*p1.w - s_*q1.w;
                    w0.x = s_*p0.x + c_*q0.x; w0.y = s_*p0.y + c_*q0.y;
                    w0.z = s_*p0.z + c_*q0.z; w0.w = s_*p0.w + c_*q0.w;
                    w1.x = s_*p1.x + c_*q1.x; w1.y = s_*p1.y + c_*q1.y;
                    w1.z = s_*p1.z + c_*q1.z; w1.w = s_*p1.w + c_*q1.w;
                    *(float4*)(vi)     = u0; *(float4*)(vi + 4) = u1;
                    *(float4*)(vj)     = w0; *(float4*)(vj + 4) = w1;
                    if (lane == 0) {
                        float cc = c_*c_, ss2 = s_*s_, cs2 = 2.f*c_*s_;
                        cn[ci] = cc*aa - cs2*gg + ss2*bb;
                        cn[cj] = ss2*aa + cs2*gg + cc*bb;
                    }
                }
                __syncthreads();
            }
        }
    }

    // exact sigma + cutoff
    if (tid < 64) {
        const float* col = Gt + tid*JP;
        float s = 0.f;
#pragma unroll
        for (int k4 = 0; k4 < 16; k4++) {
            float4 v = *(const float4*)(col + 4*k4);
            s = fmaf(v.x, v.x, s); s = fmaf(v.y, v.y, s);
            s = fmaf(v.z, v.z, s); s = fmaf(v.w, v.w, s);
        }
        svec[tid] = sqrtf(s);
    }
    __syncthreads();
    if (tid < 64) {
        float smax = 0.f;
        for (int c = 0; c < 64; c++) smax = fmaxf(smax, svec[c]);
        float cut = 7.62939453125e-5f * smax;
        float s = svec[tid];
        wv[bh*64 + tid] = (s > cut) ? 1.0f / (s * s) : 0.0f;
    }
    for (int i = tid; i < 4096; i += 256) {
        int c = i >> 6, r = i & 63;
        Gout[(size_t)bh*4096 + i] = Gt[c*JP + r];
        Vout[(size_t)bh*4096 + i] = Vt[c*JP + r];
    }
}

// ---------------------------------------------------------------------------
// MEGA kernel: blocks [0,32) jacobi | [32,1568) Q/K/V projections.
// ---------------------------------------------------------------------------
__global__ __launch_bounds__(256, 2) void mega_kernel(
    const __half* __restrict__ xh, const __half* __restrict__ xl,
    const __half* __restrict__ wh, const __half* __restrict__ wl,
    float* __restrict__ QKV,
    const float* __restrict__ Qlm, const float* __restrict__ Klm,
    float* __restrict__ Gout, float* __restrict__ Vout, float* __restrict__ wv)
{
    extern __shared__ __align__(128) char smem[];
    int bx = blockIdx.x;
    if (bx < 32) {
        dev_jacobi(smem, bx, Qlm, Klm, Gout, Vout, wv);
    } else {
        int idx = bx - 32;             // 0..1535
        int z = idx >> 9;              // 0,1,2 -> Wq,Wk,Wv
        int rem = idx & 511;
        dev_gemm3(smem, (rem >> 3) * 128, (rem & 7) * 128,
                  xh, xl,
                  wh + (size_t)z * DMODEL * DMODEL,
                  wl + (size_t)z * DMODEL * DMODEL,
                  QKV + (size_t)z * NROWS * DMODEL, DMODEL, DMODEL);
    }
}

// ---------------------------------------------------------------------------
// scores (standalone, 256 threads): s = (X_row(t) . Ylm[mi]) / 8.
// idx: zz = idx>>9 (0: Q·Klm softmax -> A; 1: K·Qlm exp -> S), bh, t-chunk.
// ---------------------------------------------------------------------------
__global__ __launch_bounds__(256) void scores_kernel(
    const float* __restrict__ Q, const float* __restrict__ K,
    const float* __restrict__ Klm, const float* __restrict__ Qlm,
    float* __restrict__ A, float* __restrict__ S)
{
    extern __shared__ __align__(128) char smemc[];
    int idx = blockIdx.x;
    int zz  = idx >> 9;
    int rem = idx & 511;
    int bh  = rem >> 4;
    int tch = rem & 15;
    const float* X   = zz ? K : Q;
    const float* Ylm = zz ? Qlm : Klm;
    float* out = zz ? S : A;
    int b = bh >> 4, h = bh & 15;
    int tid = threadIdx.x;
    int t = tch * 256 + tid;

    float4* Ks = (float4*)smemc;
    float* Ssc = (float*)(smemc + 16384);

    const float4* Ysrc = (const float4*)(Ylm + (size_t)bh * 4096);
    for (int i = tid; i < 1024; i += 256) Ks[i] = Ysrc[i];
    __syncthreads();

    const float4* xrow = (const float4*)(X + ((size_t)b * T_SEQ + t) * DMODEL + h * 64);
    float q[64];
#pragma unroll
    for (int d4 = 0; d4 < 16; d4++) {
        float4 v = xrow[d4];
        q[4*d4+0]=v.x; q[4*d4+1]=v.y; q[4*d4+2]=v.z; q[4*d4+3]=v.w;
    }
    for (int mi = 0; mi < 64; mi++) {
        float acc = 0.f;
#pragma unroll
        for (int d4 = 0; d4 < 16; d4++) {
            float4 k4 = Ks[mi*16 + d4];
            acc = fmaf(q[4*d4+0], k4.x, acc);
            acc = fmaf(q[4*d4+1], k4.y, acc);
            acc = fmaf(q[4*d4+2], k4.z, acc);
            acc = fmaf(q[4*d4+3], k4.w, acc);
        }
        Ssc[mi*256 + tid] = acc * 0.125f;
    }
    float* orow = out + ((size_t)bh * T_SEQ + t) * 64;
    if (zz == 0) {
        float m = -INFINITY;
        for (int mi = 0; mi < 64; mi++) m = fmaxf(m, Ssc[mi*256 + tid]);
        float z = 0.f;
        for (int mi = 0; mi < 64; mi++) {
            float e = expf(Ssc[mi*256 + tid] - m);
            Ssc[mi*256 + tid] = e; z += e;
        }
        float inv = 1.0f / z;
        for (int mi = 0; mi < 64; mi += 4) {
            float4 o = make_float4(Ssc[(mi+0)*256+tid]*inv, Ssc[(mi+1)*256+tid]*inv,
                                   Ssc[(mi+2)*256+tid]*inv, Ssc[(mi+3)*256+tid]*inv);
            *(float4*)(orow + mi) = o;
        }
    } else {
        for (int mi = 0; mi < 64; mi += 4) {
            float4 o = make_float4(expf(Ssc[(mi+0)*256+tid]), expf(Ssc[(mi+1)*256+tid]),
                                   expf(Ssc[(mi+2)*256+tid]), expf(Ssc[(mi+3)*256+tid]));
            *(float4*)(orow + mi) = o;
        }
    }
}

// ---------------------------------------------------------------------------
// BV partials over 512-row chunks: part = E^T V + per-column sums of E.
// ---------------------------------------------------------------------------
__global__ __launch_bounds__(256) void bv_partial_kernel(
    const float* __restrict__ Se, const float* __restrict__ V,
    float* __restrict__ part, float* __restrict__ csump)
{
    int chunk = blockIdx.x, bh = blockIdx.y;
    int b = bh >> 4, h = bh & 15;
    __shared__ float Es[64][65];
    __shared__ float Vs[64][65];
    __shared__ float sred[256];
    int tid = threadIdx.x;
    int ti = tid >> 4, tj = tid & 15;
    float acc[4][4] = {};
    float cs = 0.f;
    for (int t0 = chunk*512; t0 < chunk*512 + 512; t0 += 64) {
        __syncthreads();
        for (int i = tid; i < 4096; i += 256) {
            int r = i >> 6, c = i & 63;
            float e = Se[((size_t)bh*T_SEQ + t0 + r)*64 + c];
            Es[r][c] = e;
            cs += e;
            Vs[r][c] = V[((size_t)b*T_SEQ + t0 + r)*DMODEL + h*64 + c];
        }
        __syncthreads();
#pragma unroll 4
        for (int r = 0; r < 64; r++) {
            float a[4], bb[4];
#pragma unroll
            for (int x = 0; x < 4; x++) a[x]  = Es[r][ti*4+x];
#pragma unroll
            for (int y = 0; y < 4; y++) bb[y] = Vs[r][tj*4+y];
#pragma unroll
            for (int x = 0; x < 4; x++)
#pragma unroll
                for (int y = 0; y < 4; y++)
                    acc[x][y] = fmaf(a[x], bb[y], acc[x][y]);
        }
    }
    float* dst = part + ((size_t)(bh*8 + chunk)) * 4096;
#pragma unroll
    for (int x = 0; x < 4; x++)
#pragma unroll
        for (int y = 0; y < 4; y++)
            dst[(ti*4+x)*64 + tj*4+y] = acc[x][y];
    sred[tid] = cs;
    __syncthreads();
    if (tid < 64)
        csump[(size_t)(bh*8 + chunk)*64 + tid] =
            sred[tid] + sred[tid+64] + sred[tid+128] + sred[tid+192];
}

// ---------------------------------------------------------------------------
// pinv apply: BV = (sum partials)/colsum;  CBV = V * diag(w) * G^T * BV.
// G, V inputs dense COLUMN-major.
// ---------------------------------------------------------------------------
__global__ __launch_bounds__(256) void pinv_apply_kernel(
    const float* __restrict__ Gin, const float* __restrict__ Vin,
    const float* __restrict__ wv,
    const float* __restrict__ BVp, const float* __restrict__ csump,
    float* __restrict__ CBV)
{
    extern __shared__ float sp[];
    float* Gs   = sp;
    float* Vs   = sp + 4160;
    float* W    = sp + 8320;
    float* wvec = sp + 12480;
    float* dvec = sp + 12544;
    int bh = blockIdx.x;
    int tid = threadIdx.x;
    int ti = tid >> 4, tj = tid & 15;

    for (int i = tid; i < 4096; i += 256) {
        int c = i >> 6, q = i & 63;
        Gs[c*65 + q] = Gin[(size_t)bh*4096 + i];
        Vs[c*65 + q] = Vin[(size_t)bh*4096 + i];
    }
    if (tid < 64) {
        wvec[tid] = wv[bh*64 + tid];
        float den = 0.f;
#pragma unroll
        for (int ch = 0; ch < 8; ch++) den += csump[(size_t)(bh*8 + ch)*64 + tid];
        dvec[tid] = 1.0f / den;
    }
    __syncthreads();

    for (int i = tid; i < 4096; i += 256) {
        float s = 0.f;
#pragma unroll
        for (int ch = 0; ch < 8; ch++) s += BVp[((size_t)(bh*8 + ch))*4096 + i];
        W[(i >> 6)*65 + (i & 63)] = s * dvec[i >> 6];
    }
    __syncthreads();

    float t1[4][4] = {};
    for (int q = 0; q < 64; q++) {
        float a[4], bb[4];
#pragma unroll
        for (int x = 0; x < 4; x++) a[x]  = Gs[(ti*4+x)*65 + q];
#pragma unroll
        for (int y = 0; y < 4; y++) bb[y] = W[q*65 + tj*4+y];
#pragma unroll
        for (int x = 0; x < 4; x++)
#pragma unroll
            for (int y = 0; y < 4; y++)
                t1[x][y] = fmaf(a[x], bb[y], t1[x][y]);
    }
#pragma unroll
    for (int x = 0; x < 4; x++) {
        float w = wvec[ti*4+x];
#pragma unroll
        for (int y = 0; y < 4; y++) t1[x][y] *= w;
    }
    __syncthreads();
#pragma unroll
    for (int x = 0; x < 4; x++)
#pragma unroll
        for (int y = 0; y < 4; y++)
            Gs[(ti*4+x)*65 + tj*4+y] = t1[x][y];
    __syncthreads();

    float cb[4][4] = {};
    for (int q = 0; q < 64; q++) {
        float a[4], bb[4];
#pragma unroll
        for (int x = 0; x < 4; x++) a[x]  = Vs[q*65 + ti*4+x];
#pragma unroll
        for (int y = 0; y < 4; y++) bb[y] = Gs[q*65 + tj*4+y];
#pragma unroll
        for (int x = 0; x < 4; x++)
#pragma unroll
            for (int y = 0; y < 4; y++)
                cb[x][y] = fmaf(a[x], bb[y], cb[x][y]);
    }
#pragma unroll
    for (int x = 0; x < 4; x++)
#pragma unroll
        for (int y = 0; y < 4; y++)
            CBV[(size_t)bh*4096 + (ti*4+x)*64 + tj*4+y] = cb[x][y];
}

// ---------------------------------------------------------------------------
// Y = A_hat @ CBV per head -> fp16 hi + lo (merged-head layout).
// ---------------------------------------------------------------------------
__global__ __launch_bounds__(256) void av_kernel(
    const float* __restrict__ Ahat, const float* __restrict__ CBV,
    __half* __restrict__ ahp, __half* __restrict__ alp)
{
    int bh = blockIdx.y;
    int b = bh >> 4, hh = bh & 15;
    int t0 = blockIdx.x * 64;
    __shared__ float As[64*65];
    __shared__ float Cs[64*65];
    int tid = threadIdx.x;
    for (int i = tid; i < 4096; i += 256) {
        int tl = i >> 6, c = i & 63;
        As[c*65 + tl] = Ahat[((size_t)bh*T_SEQ + t0 + tl)*64 + c];
        Cs[tl*65 + c] = CBV[(size_t)bh*4096 + i];
    }
    __syncthreads();
    int ti = tid >> 4, tj = tid & 15;
    float acc[4][4] = {};
    for (int c = 0; c < 64; c++) {
        float a[4], bb[4];
#pragma unroll
        for (int x = 0; x < 4; x++) a[x]  = As[c*65 + ti*4+x];
#pragma unroll
        for (int y = 0; y < 4; y++) bb[y] = Cs[c*65 + tj*4+y];
#pragma unroll
        for (int x = 0; x < 4; x++)
#pragma unroll
            for (int y = 0; y < 4; y++)
                acc[x][y] = fmaf(a[x], bb[y], acc[x][y]);
    }
#pragma unroll
    for (int x = 0; x < 4; x++) {
        size_t idx = ((size_t)b*T_SEQ + t0 + ti*4 + x)*DMODEL + hh*64 + tj*4;
#pragma unroll
        for (int y = 0; y < 4; y += 2) {
            float v0 = acc[x][y], v1 = acc[x][y+1];
            __half h0 = __float2half(v0);
            __half h1 = __float2half(v1);
            __half2 Hp, Lp;
            Hp.x = h0; Hp.y = h1;
            Lp.x = __float2half(v0 - __half2float(h0));
            Lp.y = __float2half(v1 - __half2float(h1));
            *(__half2*)(ahp + idx + y) = Hp;
            *(__half2*)(alp + idx + y) = Lp;
        }
    }
}

// ---------------------------------------------------------------------------
extern "C" void kernel_launch(void* const* d_in, const int* in_sizes, int n_in,
                              void* d_out, int out_size)
{
    (void)in_sizes; (void)n_in; (void)out_size;
    const float* x = (const float*)d_in[0];
    const float* Wq = (const float*)d_in[1];
    const float* Wk = (const float*)d_in[2];
    const float* Wv = (const float*)d_in[3];
    const float* Wo = (const float*)d_in[4];
    float* out = (float*)d_out;

    float *QKV, *A, *S, *xlm, *Qlm, *Klm, *CBV, *BVp, *csump, *Gm, *Vmg, *wv;
    __half *xh, *xl, *wh, *wl, *ah, *al;
    cudaGetSymbolAddress((void**)&QKV,   g_QKV);
    cudaGetSymbolAddress((void**)&A,     g_A);
    cudaGetSymbolAddress((void**)&S,     g_S);
    cudaGetSymbolAddress((void**)&xlm,   g_xlm);
    cudaGetSymbolAddress((void**)&Qlm,   g_Qlm);
    cudaGetSymbolAddress((void**)&Klm,   g_Klm);
    cudaGetSymbolAddress((void**)&CBV,   g_CBV);
    cudaGetSymbolAddress((void**)&BVp,   g_BVpart);
    cudaGetSymbolAddress((void**)&csump, g_csump);
    cudaGetSymbolAddress((void**)&Gm,    g_Gm);
    cudaGetSymbolAddress((void**)&Vmg,   g_Vm);
    cudaGetSymbolAddress((void**)&wv,    g_wv);
    cudaGetSymbolAddress((void**)&xh,    g_xh);
    cudaGetSymbolAddress((void**)&xl,    g_xl);
    cudaGetSymbolAddress((void**)&wh,    g_wh);
    cudaGetSymbolAddress((void**)&wl,    g_wl);
    cudaGetSymbolAddress((void**)&ah,    g_ah);
    cudaGetSymbolAddress((void**)&al,    g_al);

    float* Q = QKV;
    float* K = QKV + (size_t)NROWS * DMODEL;
    float* V = QKV + 2 * (size_t)NROWS * DMODEL;

    cudaFuncSetAttribute(gemm3_kernel,
                         cudaFuncAttributeMaxDynamicSharedMemorySize, G3_SMEM);
    cudaFuncSetAttribute(mega_kernel,
                         cudaFuncAttributeMaxDynamicSharedMemorySize, G3_SMEM);
    cudaFuncSetAttribute(scores_kernel,
                         cudaFuncAttributeMaxDynamicSharedMemorySize, G3_SMEM);
    cudaFuncSetAttribute(pinv_apply_kernel,
                         cudaFuncAttributeMaxDynamicSharedMemorySize, 50432);

    // L1: all splits
    split_all_kernel<<<12288, 256>>>((const float4*)x,
        (const float4*)Wq, (const float4*)Wk, (const float4*)Wv, (const float4*)Wo,
        (__half2*)xh, (__half2*)xl, (__half2*)wh, (__half2*)wl);

    // L2: segment means of x (exact fp32)
    xlm_kernel<<<128, 256>>>(x, xlm);

    // L3: landmark projections Qlm/Klm = xlm @ W^T (exact fp32)
    lmgemm_kernel<<<dim3(16, 2), 256>>>(xlm, Wq, Wk, Qlm, Klm);

    // L4: MEGA = jacobi(32) | Q/K/V projections(1536)   <-- profiled slot
    mega_kernel<<<1568, 256, G3_SMEM>>>(xh, xl, wh, wl, QKV,
                                        Qlm, Klm, Gm, Vmg, wv);

    // L5: scores (A softmax / S exp)
    scores_kernel<<<1024, 256, G3_SMEM>>>(Q, K, Klm, Qlm, A, S);

    // L6: BV partials
    bv_partial_kernel<<<dim3(8, NBH), 256>>>(S, V, BVp, csump);

    // L7: pinv apply (BV reduce + CBV)
    pinv_apply_kernel<<<NBH, 256, 50432>>>(Gm, Vmg, wv, BVp, csump, CBV);

    // L8: A_hat @ CBV
    av_kernel<<<dim3(T_SEQ/64, NBH), 256>>>(A, CBV, ah, al);

    // L9: out projection (3-term)
    dim3 go(DMODEL/128, NROWS/128);
    gemm3_kernel<<<go, 256, G3_SMEM>>>(ah, al,
                                       wh + 3*(size_t)DMODEL*DMODEL,
                                       wl + 3*(size_t)DMODEL*DMODEL, out,
                                       DMODEL, DMODEL);
}

// round 16
// speedup vs baseline: 1.1530x; 1.1530x over previous
#include <cuda_runtime.h>
#include <cuda_fp16.h>
#include <math.h>
#include <stdint.h>

// Problem constants: B=2, T=4096, d_model=1024, H=16, d_head=64, m=64
#define T_SEQ 4096
#define DMODEL 1024
#define NBH    32      // B*H
#define NROWS  8192    // B*T
#define NSWEEP 12

// ---------------- device scratch (no runtime allocation allowed) ----------------
__device__ __align__(16) float g_QKV[3 * NROWS * DMODEL];   // Q | K | V
__device__ __align__(16) float g_A[NBH * T_SEQ * 64];       // A_hat
__device__ __align__(16) float g_S[NBH * T_SEQ * 64];       // exp(B scores)
__device__ __align__(16) float g_xlm[128 * DMODEL];         // segment means of x
__device__ __align__(16) float g_Qlm[NBH * 64 * 64];
__device__ __align__(16) float g_Klm[NBH * 64 * 64];
__device__ __align__(16) float g_CBV[NBH * 64 * 64];
__device__ __align__(16) float g_BVpart[NBH * 8 * 64 * 64];
__device__ float g_csump[NBH * 8 * 64];
// Jacobi SVD intermediates (COLUMN-major: out[c*64+r] = M[r][c])
__device__ __align__(16) float g_Gm[NBH * 64 * 64];
__device__ __align__(16) float g_Vm[NBH * 64 * 64];
__device__ float g_wv[NBH * 64];
// QK-done counter for in-mega gating
__device__ unsigned int g_qkdone;
// fp16 splits
__device__ __align__(16) __half g_xh[NROWS * DMODEL];
__device__ __align__(16) __half g_xl[NROWS * DMODEL];
__device__ __align__(16) __half g_wh[4][DMODEL * DMODEL];
__device__ __align__(16) __half g_wl[4][DMODEL * DMODEL];
__device__ __align__(16) __half g_ah[NROWS * DMODEL];
__device__ __align__(16) __half g_al[NROWS * DMODEL];

// =====================  helpers  =====================
__device__ __forceinline__ uint32_t smem_u32(const void* p) {
    return (uint32_t)__cvta_generic_to_shared(p);
}
__device__ __forceinline__ void cp16(uint32_t dst, const void* src) {
    asm volatile("cp.async.cg.shared.global [%0], [%1], 16;" :: "r"(dst), "l"(src));
}
__device__ __forceinline__ void ldsm_x4(uint32_t* r, uint32_t addr) {
    asm volatile("ldmatrix.sync.aligned.m8n8.x4.shared.b16 {%0,%1,%2,%3}, [%4];"
        : "=r"(r[0]), "=r"(r[1]), "=r"(r[2]), "=r"(r[3]) : "r"(addr));
}
#define MMA16816F(d, a, b) \
    asm volatile("mma.sync.aligned.m16n8k16.row.col.f32.f16.f16.f32 " \
        "{%0,%1,%2,%3},{%4,%5,%6,%7},{%8,%9},{%0,%1,%2,%3};" \
        : "+f"((d)[0]), "+f"((d)[1]), "+f"((d)[2]), "+f"((d)[3]) \
        : "r"((a)[0]), "r"((a)[1]), "r"((a)[2]), "r"((a)[3]), \
          "r"((b)[0]), "r"((b)[1]))

// ---------------------------------------------------------------------------
// One flat split kernel: weights (hi+lo) then x (hi+lo). Also resets gate.
// ---------------------------------------------------------------------------
__device__ __forceinline__ void split4(float4 v, __half2* hi, __half2* lo, size_t i2) {
    __half h0 = __float2half(v.x), h1 = __float2half(v.y);
    __half h2 = __float2half(v.z), h3 = __float2half(v.w);
    __half2 H0, H1, L0, L1;
    H0.x = h0; H0.y = h1; H1.x = h2; H1.y = h3;
    L0.x = __float2half(v.x - __half2float(h0));
    L0.y = __float2half(v.y - __half2float(h1));
    L1.x = __float2half(v.z - __half2float(h2));
    L1.y = __float2half(v.w - __half2float(h3));
    hi[i2] = H0; hi[i2+1] = H1;
    lo[i2] = L0; lo[i2+1] = L1;
}

__global__ void split_all_kernel(
    const float4* __restrict__ x,
    const float4* __restrict__ W0, const float4* __restrict__ W1,
    const float4* __restrict__ W2, const float4* __restrict__ W3,
    __half2* __restrict__ xh2, __half2* __restrict__ xl2,
    __half2* __restrict__ wh2, __half2* __restrict__ wl2)
{
    int idx = blockIdx.x * 256 + threadIdx.x;
    if (idx == 0) g_qkdone = 0u;            // reset gate each replay
    if (idx < 4 * 262144) {
        int w = idx >> 18;
        int i = idx & 262143;
        const float4* src = (w == 0) ? W0 : (w == 1) ? W1 : (w == 2) ? W2 : W3;
        split4(src[i], wh2, wl2, (size_t)w * 524288 + 2 * (size_t)i);
    } else {
        int j = idx - 4 * 262144;
        split4(x[j], xh2, xl2, 2 * (size_t)j);
    }
}

// ---------------------------------------------------------------------------
// xlm: segment means of x.  grid 128, 256 threads.
// ---------------------------------------------------------------------------
__global__ void xlm_kernel(const float* __restrict__ x, float* __restrict__ xlm)
{
    int m = blockIdx.x;            // 0..127
    int b = m >> 6, seg = m & 63;
    const float* base = x + ((size_t)b * T_SEQ + seg * 64) * DMODEL;
    int tid = threadIdx.x;
#pragma unroll
    for (int cc = 0; cc < 4; cc++) {
        int c = tid + cc * 256;
        float s = 0.f;
#pragma unroll 8
        for (int r = 0; r < 64; r++) s += base[(size_t)r * DMODEL + c];
        xlm[(size_t)m * DMODEL + c] = s * 0.015625f;
    }
}

// ---------------------------------------------------------------------------
// lmgemm: Qlm/Klm = xlm @ W^T  (fp32 SIMT, exact — feeds the pinv path).
// grid (16 n-tiles, 2 weights), 256 threads, float4-coalesced loads.
// ---------------------------------------------------------------------------
__global__ __launch_bounds__(256) void lmgemm_kernel(
    const float* __restrict__ xlm,
    const float* __restrict__ Wq, const float* __restrict__ Wk,
    float* __restrict__ Qlm, float* __restrict__ Klm)
{
    const float* W = blockIdx.y ? Wk : Wq;
    float* out = blockIdx.y ? Klm : Qlm;
    int n0 = blockIdx.x * 64;
    __shared__ float xs[16][132];   // [k][m]
    __shared__ float ws[16][68];    // [k][n]
    int tid = threadIdx.x;
    int ti = tid >> 3;   // 0..31 (4 rows each)
    int tj = tid & 7;    // 0..7  (8 cols each)
    float acc[4][8] = {};
    for (int k0 = 0; k0 < DMODEL; k0 += 16) {
        __syncthreads();
        // xs: 128 m x 16 k, float4 over k (coalesced 64B per m)
        for (int i = tid; i < 512; i += 256) {
            int m = i >> 2, kq = i & 3;
            float4 v = *(const float4*)&xlm[(size_t)m * DMODEL + k0 + kq*4];
            xs[kq*4+0][m] = v.x; xs[kq*4+1][m] = v.y;
            xs[kq*4+2][m] = v.z; xs[kq*4+3][m] = v.w;
        }
        // ws: 64 n x 16 k
        if (tid < 256) {
            int i = tid;
            if (i < 256) {
                int n = i >> 2, kq = i & 3;
                float4 v = *(const float4*)&W[(size_t)(n0 + n) * DMODEL + k0 + kq*4];
                ws[kq*4+0][n] = v.x; ws[kq*4+1][n] = v.y;
                ws[kq*4+2][n] = v.z; ws[kq*4+3][n] = v.w;
            }
        }
        __syncthreads();
#pragma unroll
        for (int kk = 0; kk < 16; kk++) {
            float a[4], b[8];
#pragma unroll
            for (int x2 = 0; x2 < 4; x2++) a[x2] = xs[kk][ti*4 + x2];
#pragma unroll
            for (int y = 0; y < 8; y++) b[y] = ws[kk][tj*8 + y];
#pragma unroll
            for (int x2 = 0; x2 < 4; x2++)
#pragma unroll
                for (int y = 0; y < 8; y++)
                    acc[x2][y] = fmaf(a[x2], b[y], acc[x2][y]);
        }
    }
#pragma unroll
    for (int x2 = 0; x2 < 4; x2++) {
        int m = ti*4 + x2;
        int b = m >> 6, mi = m & 63;
#pragma unroll
        for (int y = 0; y < 8; y++) {
            int n = n0 + tj*8 + y;
            int h = n >> 6, d = n & 63;
            out[((size_t)(b*16 + h) * 64 + mi) * 64 + d] = acc[x2][y];
        }
    }
}

// ---------------------------------------------------------------------------
// 3-term NT GEMM tile body: C = Ah*Bh + Ah*Bl + Al*Bh (fp32 acc).
// ---------------------------------------------------------------------------
#define GM_ROWB  80
#define GM_TILE  (128 * GM_ROWB)      // 10240
#define G3_STAGE (4 * GM_TILE)        // 40960
#define G3_SMEM  (2 * G3_STAGE)       // 81920

__device__ void dev_gemm3(char* smem, int m0, int n0,
    const __half* __restrict__ Ahi, const __half* __restrict__ Alo,
    const __half* __restrict__ Bhi, const __half* __restrict__ Blo,
    float* __restrict__ C, int N, int K)
{
    const uint32_t sb = smem_u32(smem);
    const int tid = threadIdx.x;
    const int wid = tid >> 5, lane = tid & 31;
    const int wr = (wid & 3) * 32;
    const int wc = (wid >> 2) * 64;
    const int lrow = tid >> 2;
    const int lseg = tid & 3;

    const int nchunks = K >> 5;

    auto load_stage = [&](int s, int kc) {
        uint32_t st = sb + s * G3_STAGE;
#pragma unroll
        for (int i = 0; i < 2; i++) {
            int row = lrow + i * 64;
            uint32_t off = row * GM_ROWB + lseg * 16;
            cp16(st +             off, Ahi + (size_t)(m0 + row) * K + kc + lseg * 8);
            cp16(st + GM_TILE   + off, Alo + (size_t)(m0 + row) * K + kc + lseg * 8);
            cp16(st + 2*GM_TILE + off, Bhi + (size_t)(n0 + row) * K + kc + lseg * 8);
            cp16(st + 3*GM_TILE + off, Blo + (size_t)(n0 + row) * K + kc + lseg * 8);
        }
        asm volatile("cp.async.commit_group;" ::: "memory");
    };

    load_stage(0, 0);
    load_stage(1, 32);

    float accF[2][8][4];
#pragma unroll
    for (int mt = 0; mt < 2; mt++)
#pragma unroll
        for (int nt = 0; nt < 8; nt++)
#pragma unroll
            for (int q = 0; q < 4; q++) accF[mt][nt][q] = 0.f;

    const uint32_t aBase = (uint32_t)(wr + (lane & 15)) * GM_ROWB + (uint32_t)(lane >> 4) * 16;
    const uint32_t bBase = (uint32_t)(wc + (lane & 7) + ((lane >> 4) * 8)) * GM_ROWB
                         + (uint32_t)((lane >> 3) & 1) * 16;

    const int fr = lane >> 2;
    const int fc = (lane & 3) * 2;

    for (int c = 0; c < nchunks; c++) {
        int s = c & 1;
        asm volatile("cp.async.wait_group 1;" ::: "memory");
        __syncthreads();
        uint32_t st  = sb + s * G3_STAGE;
        uint32_t tAH = st;
        uint32_t tAL = st + GM_TILE;
        uint32_t tBH = st + 2*GM_TILE;
        uint32_t tBL = st + 3*GM_TILE;

#pragma unroll
        for (int k16 = 0; k16 < 2; k16++) {
            uint32_t kb = k16 * 32;
            uint32_t aH[2][4], aL[2][4];
#pragma unroll
            for (int mt = 0; mt < 2; mt++) {
                uint32_t ao = aBase + mt * 16 * GM_ROWB + kb;
                ldsm_x4(aH[mt], tAH + ao);
                ldsm_x4(aL[mt], tAL + ao);
            }
            uint32_t bH[8][2], bL[8][2];
#pragma unroll
            for (int p = 0; p < 4; p++) {
                uint32_t bo = bBase + p * 16 * GM_ROWB + kb;
                uint32_t tH[4], tL[4];
                ldsm_x4(tH, tBH + bo);
                ldsm_x4(tL, tBL + bo);
                bH[2*p][0] = tH[0]; bH[2*p][1] = tH[1];
                bH[2*p+1][0] = tH[2]; bH[2*p+1][1] = tH[3];
                bL[2*p][0] = tL[0]; bL[2*p][1] = tL[1];
                bL[2*p+1][0] = tL[2]; bL[2*p+1][1] = tL[3];
            }
#pragma unroll
            for (int mt = 0; mt < 2; mt++)
#pragma unroll
                for (int nt = 0; nt < 8; nt++)
                    MMA16816F(accF[mt][nt], aH[mt], bH[nt]);
#pragma unroll
            for (int mt = 0; mt < 2; mt++)
#pragma unroll
                for (int nt = 0; nt < 8; nt++)
                    MMA16816F(accF[mt][nt], aH[mt], bL[nt]);
#pragma unroll
            for (int mt = 0; mt < 2; mt++)
#pragma unroll
                for (int nt = 0; nt < 8; nt++)
                    MMA16816F(accF[mt][nt], aL[mt], bH[nt]);
        }
        __syncthreads();
        if (c + 2 < nchunks) {
            load_stage(s, (c + 2) * 32);
        } else {
            asm volatile("cp.async.commit_group;" ::: "memory");
        }
    }

#pragma unroll
    for (int mt = 0; mt < 2; mt++) {
#pragma unroll
        for (int nt = 0; nt < 8; nt++) {
            int row = m0 + wr + mt*16 + fr;
            int col = n0 + wc + nt*8 + fc;
            *(float2*)(C + (size_t)row * N + col) =
                make_float2(accF[mt][nt][0], accF[mt][nt][1]);
            *(float2*)(C + (size_t)(row + 8) * N + col) =
                make_float2(accF[mt][nt][2], accF[mt][nt][3]);
        }
    }
}

// standalone gemm3 kernel (out projection)
__global__ __launch_bounds__(256, 2) void gemm3_kernel(
    const __half* __restrict__ Ahi, const __half* __restrict__ Alo,
    const __half* __restrict__ Bhi, const __half* __restrict__ Blo,
    float* __restrict__ C, int N, int K)
{
    extern __shared__ __align__(128) char smem[];
    dev_gemm3(smem, blockIdx.y * 128, blockIdx.x * 128,
              Ahi, Alo, Bhi, Blo, C, N, K);
}

// ---------------------------------------------------------------------------
// Jacobi SVD body. Column-major pitch-68, float4 ops, tracked norms,
// fast-math on angle path only; sigma/cutoff/softmax exact.
// ---------------------------------------------------------------------------
#define JP 68

__device__ void dev_jacobi(char* smemc, int bh,
    const float* __restrict__ Qlm, const float* __restrict__ Klm,
    float* __restrict__ Gout, float* __restrict__ Vout, float* __restrict__ wv)
{
    float* sp = (float*)smemc;
    float* Gt   = sp;             // 64*68
    float* Vt   = sp + 4352;      // 64*68
    float* cn   = sp + 8704;      // 64
    float* svec = sp + 8768;      // 64
    int tid = threadIdx.x;
    int ti = tid >> 4, tj = tid & 15;

    for (int i = tid; i < 4096; i += 256) {
        int r = i >> 6, c = i & 63;
        Gt[r*JP + c] = Qlm[(size_t)bh*4096 + i];
        Vt[r*JP + c] = Klm[(size_t)bh*4096 + i];
    }
    __syncthreads();

    float cacc[4][4] = {};
    for (int d = 0; d < 64; d++) {
        float qa[4], kb[4];
#pragma unroll
        for (int x = 0; x < 4; x++) qa[x] = Gt[(ti*4+x)*JP + d];
#pragma unroll
        for (int y = 0; y < 4; y++) kb[y] = Vt[(tj*4+y)*JP + d];
#pragma unroll
        for (int x = 0; x < 4; x++)
#pragma unroll
            for (int y = 0; y < 4; y++)
                cacc[x][y] = fmaf(qa[x], kb[y], cacc[x][y]);
    }
    __syncthreads();
#pragma unroll
    for (int x = 0; x < 4; x++)
#pragma unroll
        for (int y = 0; y < 4; y++)
            Vt[(ti*4+x)*JP + tj*4+y] = cacc[x][y] * 0.125f;
    __syncthreads();

    // row softmax (exact)
    if (tid < 64) {
        float mx = -INFINITY;
        for (int c = 0; c < 64; c++) mx = fmaxf(mx, Vt[tid*JP + c]);
        float z = 0.f;
        for (int c = 0; c < 64; c++) {
            float e = expf(Vt[tid*JP + c] - mx);
            Vt[tid*JP + c] = e; z += e;
        }
        float inv = 1.f / z;
        for (int c = 0; c < 64; c++) Vt[tid*JP + c] *= inv;
    }
    __syncthreads();

    for (int i = tid; i < 4096; i += 256) {
        int r = i >> 6, c = i & 63;
        Gt[c*JP + r] = Vt[r*JP + c];
    }
    __syncthreads();
    for (int i = tid; i < 4096; i += 256) {
        int r = i >> 6, c = i & 63;
        Vt[c*JP + r] = (r == c) ? 1.f : 0.f;
    }
    __syncthreads();

    {
        int p = tid >> 3, lane = tid & 7;
        for (int sw = 0; sw < NSWEEP; sw++) {
            if (tid < 64) {
                const float* col = Gt + tid*JP;
                float s = 0.f;
#pragma unroll
                for (int k4 = 0; k4 < 16; k4++) {
                    float4 v = *(const float4*)(col + 4*k4);
                    s = fmaf(v.x, v.x, s); s = fmaf(v.y, v.y, s);
                    s = fmaf(v.z, v.z, s); s = fmaf(v.w, v.w, s);
                }
                cn[tid] = s;
            }
            __syncthreads();

            for (int r = 0; r < 63; r++) {
                int ci, cj;
                if (p == 0) { ci = 63; cj = r; }
                else { ci = (r + p) % 63; cj = (r - p + 63) % 63; }
                float* gi = Gt + ci*JP + 8*lane;
                float* gj = Gt + cj*JP + 8*lane;
                float4 a0 = *(float4*)(gi);
                float4 a1 = *(float4*)(gi + 4);
                float4 b0 = *(float4*)(gj);
                float4 b1 = *(float4*)(gj + 4);
                float gg = a0.x*b0.x + a0.y*b0.y + a0.z*b0.z + a0.w*b0.w
                         + a1.x*b1.x + a1.y*b1.y + a1.z*b1.z + a1.w*b1.w;
#pragma unroll
                for (int o = 4; o > 0; o >>= 1)
                    gg += __shfl_xor_sync(0xffffffffu, gg, o);
                float aa = cn[ci], bb = cn[cj];
                float c_ = 1.f, s_ = 0.f;
                if (fabsf(gg) > 1e-30f) {
                    float zeta = __fdividef(bb - aa, 2.0f * gg);
                    float t = copysignf(
                        __fdividef(1.0f, fabsf(zeta) + sqrtf(fmaf(zeta, zeta, 1.0f))),
                        zeta);
                    c_ = rsqrtf(fmaf(t, t, 1.0f));
                    s_ = c_ * t;
                }
                if (s_ != 0.f) {
                    float4 n0, n1, m0, m1;
                    n0.x = c_*a0.x - s_*b0.x; n0.y = c_*a0.y - s_*b0.y;
                    n0.z = c_*a0.z - s_*b0.z; n0.w = c_*a0.w - s_*b0.w;
                    n1.x = c_*a1.x - s_*b1.x; n1.y = c_*a1.y - s_*b1.y;
                    n1.z = c_*a1.z - s_*b1.z; n1.w = c_*a1.w - s_*b1.w;
                    m0.x = s_*a0.x + c_*b0.x; m0.y = s_*a0.y + c_*b0.y;
                    m0.z = s_*a0.z + c_*b0.z; m0.w = s_*a0.w + c_*b0.w;
                    m1.x = s_*a1.x + c_*b1.x; m1.y = s_*a1.y + c_*b1.y;
                    m1.z = s_*a1.z + c_*b1.z; m1.w = s_*a1.w + c_*b1.w;
                    *(float4*)(gi)     = n0; *(float4*)(gi + 4) = n1;
                    *(float4*)(gj)     = m0; *(float4*)(gj + 4) = m1;
                    float* vi = Vt + ci*JP + 8*lane;
                    float* vj = Vt + cj*JP + 8*lane;
                    float4 p0 = *(float4*)(vi), p1 = *(float4*)(vi + 4);
                    float4 q0 = *(float4*)(vj), q1 = *(float4*)(vj + 4);
                    float4 u0, u1, w0, w1;
                    u0.x = c_*p0.x - s_*q0.x; u0.y = c_*p0.y - s_*q0.y;
                    u0.z = c_*p0.z - s_*q0.z; u0.w = c_*p0.w - s_*q0.w;
                    u1.x = c_*p1.x - s_*q1.x; u1.y = c_*p1.y - s_*q1.y;
                    u1.z = c_*p1.z - s_*q1.z; u1.w = c_*p1.w - s_*q1.w;
                    w0.x = s_*p0.x + c_*q0.x; w0.y = s_*p0.y + c_*q0.y;
                    w0.z = s_*p0.z + c_*q0.z; w0.w = s_*p0.w + c_*q0.w;
                    w1.x = s_*p1.x + c_*q1.x; w1.y = s_*p1.y + c_*q1.y;
                    w1.z = s_*p1.z + c_*q1.z; w1.w = s_*p1.w + c_*q1.w;
                    *(float4*)(vi)     = u0; *(float4*)(vi + 4) = u1;
                    *(float4*)(vj)     = w0; *(float4*)(vj + 4) = w1;
                    if (lane == 0) {
                        float cc = c_*c_, ss2 = s_*s_, cs2 = 2.f*c_*s_;
                        cn[ci] = cc*aa - cs2*gg + ss2*bb;
                        cn[cj] = ss2*aa + cs2*gg + cc*bb;
                    }
                }
                __syncthreads();
            }
        }
    }

    // exact sigma + cutoff
    if (tid < 64) {
        const float* col = Gt + tid*JP;
        float s = 0.f;
#pragma unroll
        for (int k4 = 0; k4 < 16; k4++) {
            float4 v = *(const float4*)(col + 4*k4);
            s = fmaf(v.x, v.x, s); s = fmaf(v.y, v.y, s);
            s = fmaf(v.z, v.z, s); s = fmaf(v.w, v.w, s);
        }
        svec[tid] = sqrtf(s);
    }
    __syncthreads();
    if (tid < 64) {
        float smax = 0.f;
        for (int c = 0; c < 64; c++) smax = fmaxf(smax, svec[c]);
        float cut = 7.62939453125e-5f * smax;
        float s = svec[tid];
        wv[bh*64 + tid] = (s > cut) ? 1.0f / (s * s) : 0.0f;
    }
    for (int i = tid; i < 4096; i += 256) {
        int c = i >> 6, r = i & 63;
        Gout[(size_t)bh*4096 + i] = Gt[c*JP + r];
        Vout[(size_t)bh*4096 + i] = Vt[c*JP + r];
    }
}

// ---------------------------------------------------------------------------
// scores body (256 threads, 256 t per CTA).
// ---------------------------------------------------------------------------
__device__ void dev_scores(char* smemc, int idx,
    const float* __restrict__ Q, const float* __restrict__ K,
    const float* __restrict__ Klm, const float* __restrict__ Qlm,
    float* __restrict__ A, float* __restrict__ S)
{
    int zz  = idx >> 9;
    int rem = idx & 511;
    int bh  = rem >> 4;
    int tch = rem & 15;
    const float* X   = zz ? K : Q;
    const float* Ylm = zz ? Qlm : Klm;
    float* out = zz ? S : A;
    int b = bh >> 4, h = bh & 15;
    int tid = threadIdx.x;
    int t = tch * 256 + tid;

    float4* Ks = (float4*)smemc;
    float* Ssc = (float*)(smemc + 16384);

    const float4* Ysrc = (const float4*)(Ylm + (size_t)bh * 4096);
    for (int i = tid; i < 1024; i += 256) Ks[i] = Ysrc[i];
    __syncthreads();

    const float4* xrow = (const float4*)(X + ((size_t)b * T_SEQ + t) * DMODEL + h * 64);
    float q[64];
#pragma unroll
    for (int d4 = 0; d4 < 16; d4++) {
        float4 v = xrow[d4];
        q[4*d4+0]=v.x; q[4*d4+1]=v.y; q[4*d4+2]=v.z; q[4*d4+3]=v.w;
    }
    for (int mi = 0; mi < 64; mi++) {
        float acc = 0.f;
#pragma unroll
        for (int d4 = 0; d4 < 16; d4++) {
            float4 k4 = Ks[mi*16 + d4];
            acc = fmaf(q[4*d4+0], k4.x, acc);
            acc = fmaf(q[4*d4+1], k4.y, acc);
            acc = fmaf(q[4*d4+2], k4.z, acc);
            acc = fmaf(q[4*d4+3], k4.w, acc);
        }
        Ssc[mi*256 + tid] = acc * 0.125f;
    }
    float* orow = out + ((size_t)bh * T_SEQ + t) * 64;
    if (zz == 0) {
        float m = -INFINITY;
        for (int mi = 0; mi < 64; mi++) m = fmaxf(m, Ssc[mi*256 + tid]);
        float z = 0.f;
        for (int mi = 0; mi < 64; mi++) {
            float e = expf(Ssc[mi*256 + tid] - m);
            Ssc[mi*256 + tid] = e; z += e;
        }
        float inv = 1.0f / z;
        for (int mi = 0; mi < 64; mi += 4) {
            float4 o = make_float4(Ssc[(mi+0)*256+tid]*inv, Ssc[(mi+1)*256+tid]*inv,
                                   Ssc[(mi+2)*256+tid]*inv, Ssc[(mi+3)*256+tid]*inv);
            *(float4*)(orow + mi) = o;
        }
    } else {
        for (int mi = 0; mi < 64; mi += 4) {
            float4 o = make_float4(expf(Ssc[(mi+0)*256+tid]), expf(Ssc[(mi+1)*256+tid]),
                                   expf(Ssc[(mi+2)*256+tid]), expf(Ssc[(mi+3)*256+tid]));
            *(float4*)(orow + mi) = o;
        }
    }
}

// ---------------------------------------------------------------------------
// MEGA kernel:
//  [0,32)      jacobi
//  [32,1056)   Q,K projection tiles (signal g_qkdone after stores)
//  [1056,1568) V projection tiles
//  [1568,2592) scores (gated: wait for all 1024 QK tiles; deadlock-free
//              because waiters only depend on lower-indexed CTAs)
// ---------------------------------------------------------------------------
__global__ __launch_bounds__(256, 2) void mega_kernel(
    const __half* __restrict__ xh, const __half* __restrict__ xl,
    const __half* __restrict__ wh, const __half* __restrict__ wl,
    float* __restrict__ QKV,
    const float* __restrict__ Qlm, const float* __restrict__ Klm,
    float* __restrict__ A, float* __restrict__ S,
    float* __restrict__ Gout, float* __restrict__ Vout, float* __restrict__ wv)
{
    extern __shared__ __align__(128) char smem[];
    int bx = blockIdx.x;
    const float* Q = QKV;
    const float* K = QKV + (size_t)NROWS * DMODEL;
    if (bx < 32) {
        dev_jacobi(smem, bx, Qlm, Klm, Gout, Vout, wv);
    } else if (bx < 1056) {
        int idx = bx - 32;             // 0..1023
        int z = idx >> 9;              // 0,1 -> Wq,Wk
        int rem = idx & 511;
        dev_gemm3(smem, (rem >> 3) * 128, (rem & 7) * 128,
                  xh, xl,
                  wh + (size_t)z * DMODEL * DMODEL,
                  wl + (size_t)z * DMODEL * DMODEL,
                  QKV + (size_t)z * NROWS * DMODEL, DMODEL, DMODEL);
        __threadfence();
        __syncthreads();
        if (threadIdx.x == 0) atomicAdd(&g_qkdone, 1u);
    } else if (bx < 1568) {
        int rem = bx - 1056;           // 0..511
        dev_gemm3(smem, (rem >> 3) * 128, (rem & 7) * 128,
                  xh, xl,
                  wh + 2*(size_t)DMODEL * DMODEL,
                  wl + 2*(size_t)DMODEL * DMODEL,
                  QKV + 2*(size_t)NROWS * DMODEL, DMODEL, DMODEL);
    } else {
        if (threadIdx.x == 0) {
            while (atomicAdd(&g_qkdone, 0u) < 1024u) __nanosleep(256);
        }
        __syncthreads();
        __threadfence();
        dev_scores(smem, bx - 1568, Q, K, Klm, Qlm, A, S);
    }
}

// ---------------------------------------------------------------------------
// BV partials over 512-row chunks: part = E^T V + per-column sums of E.
// ---------------------------------------------------------------------------
__global__ __launch_bounds__(256) void bv_partial_kernel(
    const float* __restrict__ Se, const float* __restrict__ V,
    float* __restrict__ part, float* __restrict__ csump)
{
    int chunk = blockIdx.x, bh = blockIdx.y;
    int b = bh >> 4, h = bh & 15;
    __shared__ float Es[64][65];
    __shared__ float Vs[64][65];
    __shared__ float sred[256];
    int tid = threadIdx.x;
    int ti = tid >> 4, tj = tid & 15;
    float acc[4][4] = {};
    float cs = 0.f;
    for (int t0 = chunk*512; t0 < chunk*512 + 512; t0 += 64) {
        __syncthreads();
        for (int i = tid; i < 4096; i += 256) {
            int r = i >> 6, c = i & 63;
            float e = Se[((size_t)bh*T_SEQ + t0 + r)*64 + c];
            Es[r][c] = e;
            cs += e;
            Vs[r][c] = V[((size_t)b*T_SEQ + t0 + r)*DMODEL + h*64 + c];
        }
        __syncthreads();
#pragma unroll 4
        for (int r = 0; r < 64; r++) {
            float a[4], bb[4];
#pragma unroll
            for (int x = 0; x < 4; x++) a[x]  = Es[r][ti*4+x];
#pragma unroll
            for (int y = 0; y < 4; y++) bb[y] = Vs[r][tj*4+y];
#pragma unroll
            for (int x = 0; x < 4; x++)
#pragma unroll
                for (int y = 0; y < 4; y++)
                    acc[x][y] = fmaf(a[x], bb[y], acc[x][y]);
        }
    }
    float* dst = part + ((size_t)(bh*8 + chunk)) * 4096;
#pragma unroll
    for (int x = 0; x < 4; x++)
#pragma unroll
        for (int y = 0; y < 4; y++)
            dst[(ti*4+x)*64 + tj*4+y] = acc[x][y];
    sred[tid] = cs;
    __syncthreads();
    if (tid < 64)
        csump[(size_t)(bh*8 + chunk)*64 + tid] =
            sred[tid] + sred[tid+64] + sred[tid+128] + sred[tid+192];
}

// ---------------------------------------------------------------------------
// pinv apply: BV = (sum partials)/colsum;  CBV = V * diag(w) * G^T * BV.
// ---------------------------------------------------------------------------
__global__ __launch_bounds__(256) void pinv_apply_kernel(
    const float* __restrict__ Gin, const float* __restrict__ Vin,
    const float* __restrict__ wv,
    const float* __restrict__ BVp, const float* __restrict__ csump,
    float* __restrict__ CBV)
{
    extern __shared__ float sp[];
    float* Gs   = sp;
    float* Vs   = sp + 4160;
    float* W    = sp + 8320;
    float* wvec = sp + 12480;
    float* dvec = sp + 12544;
    int bh = blockIdx.x;
    int tid = threadIdx.x;
    int ti = tid >> 4, tj = tid & 15;

    for (int i = tid; i < 4096; i += 256) {
        int c = i >> 6, q = i & 63;
        Gs[c*65 + q] = Gin[(size_t)bh*4096 + i];
        Vs[c*65 + q] = Vin[(size_t)bh*4096 + i];
    }
    if (tid < 64) {
        wvec[tid] = wv[bh*64 + tid];
        float den = 0.f;
#pragma unroll
        for (int ch = 0; ch < 8; ch++) den += csump[(size_t)(bh*8 + ch)*64 + tid];
        dvec[tid] = 1.0f / den;
    }
    __syncthreads();

    for (int i = tid; i < 4096; i += 256) {
        float s = 0.f;
#pragma unroll
        for (int ch = 0; ch < 8; ch++) s += BVp[((size_t)(bh*8 + ch))*4096 + i];
        W[(i >> 6)*65 + (i & 63)] = s * dvec[i >> 6];
    }
    __syncthreads();

    float t1[4][4] = {};
    for (int q = 0; q < 64; q++) {
        float a[4], bb[4];
#pragma unroll
        for (int x = 0; x < 4; x++) a[x]  = Gs[(ti*4+x)*65 + q];
#pragma unroll
        for (int y = 0; y < 4; y++) bb[y] = W[q*65 + tj*4+y];
#pragma unroll
        for (int x = 0; x < 4; x++)
#pragma unroll
            for (int y = 0; y < 4; y++)
                t1[x][y] = fmaf(a[x], bb[y], t1[x][y]);
    }
#pragma unroll
    for (int x = 0; x < 4; x++) {
        float w = wvec[ti*4+x];
#pragma unroll
        for (int y = 0; y < 4; y++) t1[x][y] *= w;
    }
    __syncthreads();
#pragma unroll
    for (int x = 0; x < 4; x++)
#pragma unroll
        for (int y = 0; y < 4; y++)
            Gs[(ti*4+x)*65 + tj*4+y] = t1[x][y];
    __syncthreads();

    float cb[4][4] = {};
    for (int q = 0; q < 64; q++) {
        float a[4], bb[4];
#pragma unroll
        for (int x = 0; x < 4; x++) a[x]  = Vs[q*65 + ti*4+x];
#pragma unroll
        for (int y = 0; y < 4; y++) bb[y] = Gs[q*65 + tj*4+y];
#pragma unroll
        for (int x = 0; x < 4; x++)
#pragma unroll
            for (int y = 0; y < 4; y++)
                cb[x][y] = fmaf(a[x], bb[y], cb[x][y]);
    }
#pragma unroll
    for (int x = 0; x < 4; x++)
#pragma unroll
        for (int y = 0; y < 4; y++)
            CBV[(size_t)bh*4096 + (ti*4+x)*64 + tj*4+y] = cb[x][y];
}

// ---------------------------------------------------------------------------
// Y = A_hat @ CBV per head -> fp16 hi + lo (merged-head layout).
// ---------------------------------------------------------------------------
__global__ __launch_bounds__(256) void av_kernel(
    const float* __restrict__ Ahat, const float* __restrict__ CBV,
    __half* __restrict__ ahp, __half* __restrict__ alp)
{
    int bh = blockIdx.y;
    int b = bh >> 4, hh = bh & 15;
    int t0 = blockIdx.x * 64;
    __shared__ float As[64*65];
    __shared__ float Cs[64*65];
    int tid = threadIdx.x;
    for (int i = tid; i < 4096; i += 256) {
        int tl = i >> 6, c = i & 63;
        As[c*65 + tl] = Ahat[((size_t)bh*T_SEQ + t0 + tl)*64 + c];
        Cs[tl*65 + c] = CBV[(size_t)bh*4096 + i];
    }
    __syncthreads();
    int ti = tid >> 4, tj = tid & 15;
    float acc[4][4] = {};
    for (int c = 0; c < 64; c++) {
        float a[4], bb[4];
#pragma unroll
        for (int x = 0; x < 4; x++) a[x]  = As[c*65 + ti*4+x];
#pragma unroll
        for (int y = 0; y < 4; y++) bb[y] = Cs[c*65 + tj*4+y];
#pragma unroll
        for (int x = 0; x < 4; x++)
#pragma unroll
            for (int y = 0; y < 4; y++)
                acc[x][y] = fmaf(a[x], bb[y], acc[x][y]);
    }
#pragma unroll
    for (int x = 0; x < 4; x++) {
        size_t idx = ((size_t)b*T_SEQ + t0 + ti*4 + x)*DMODEL + hh*64 + tj*4;
#pragma unroll
        for (int y = 0; y < 4; y += 2) {
            float v0 = acc[x][y], v1 = acc[x][y+1];
            __half h0 = __float2half(v0);
            __half h1 = __float2half(v1);
            __half2 Hp, Lp;
            Hp.x = h0; Hp.y = h1;
            Lp.x = __float2half(v0 - __half2float(h0));
            Lp.y = __float2half(v1 - __half2float(h1));
            *(__half2*)(ahp + idx + y) = Hp;
            *(__half2*)(alp + idx + y) = Lp;
        }
    }
}

// ---------------------------------------------------------------------------
extern "C" void kernel_launch(void* const* d_in, const int* in_sizes, int n_in,
                              void* d_out, int out_size)
{
    (void)in_sizes; (void)n_in; (void)out_size;
    const float* x = (const float*)d_in[0];
    const float* Wq = (const float*)d_in[1];
    const float* Wk = (const float*)d_in[2];
    const float* Wv = (const float*)d_in[3];
    const float* Wo = (const float*)d_in[4];
    float* out = (float*)d_out;

    float *QKV, *A, *S, *xlm, *Qlm, *Klm, *CBV, *BVp, *csump, *Gm, *Vmg, *wv;
    __half *xh, *xl, *wh, *wl, *ah, *al;
    cudaGetSymbolAddress((void**)&QKV,   g_QKV);
    cudaGetSymbolAddress((void**)&A,     g_A);
    cudaGetSymbolAddress((void**)&S,     g_S);
    cudaGetSymbolAddress((void**)&xlm,   g_xlm);
    cudaGetSymbolAddress((void**)&Qlm,   g_Qlm);
    cudaGetSymbolAddress((void**)&Klm,   g_Klm);
    cudaGetSymbolAddress((void**)&CBV,   g_CBV);
    cudaGetSymbolAddress((void**)&BVp,   g_BVpart);
    cudaGetSymbolAddress((void**)&csump, g_csump);
    cudaGetSymbolAddress((void**)&Gm,    g_Gm);
    cudaGetSymbolAddress((void**)&Vmg,   g_Vm);
    cudaGetSymbolAddress((void**)&wv,    g_wv);
    cudaGetSymbolAddress((void**)&xh,    g_xh);
    cudaGetSymbolAddress((void**)&xl,    g_xl);
    cudaGetSymbolAddress((void**)&wh,    g_wh);
    cudaGetSymbolAddress((void**)&wl,    g_wl);
    cudaGetSymbolAddress((void**)&ah,    g_ah);
    cudaGetSymbolAddress((void**)&al,    g_al);

    float* V = QKV + 2 * (size_t)NROWS * DMODEL;

    cudaFuncSetAttribute(gemm3_kernel,
                         cudaFuncAttributeMaxDynamicSharedMemorySize, G3_SMEM);
    cudaFuncSetAttribute(mega_kernel,
                         cudaFuncAttributeMaxDynamicSharedMemorySize, G3_SMEM);
    cudaFuncSetAttribute(pinv_apply_kernel,
                         cudaFuncAttributeMaxDynamicSharedMemorySize, 50432);

    // L1: all splits (+ gate reset)
    split_all_kernel<<<12288, 256>>>((const float4*)x,
        (const float4*)Wq, (const float4*)Wk, (const float4*)Wv, (const float4*)Wo,
        (__half2*)xh, (__half2*)xl, (__half2*)wh, (__half2*)wl);

    // L2: segment means of x (exact fp32)
    xlm_kernel<<<128, 256>>>(x, xlm);

    // L3: landmark projections Qlm/Klm = xlm @ W^T (exact fp32)
    lmgemm_kernel<<<dim3(16, 2), 256>>>(xlm, Wq, Wk, Qlm, Klm);

    // L4: MEGA = jacobi | QK | V | gated scores     <-- profiled slot
    mega_kernel<<<2592, 256, G3_SMEM>>>(xh, xl, wh, wl, QKV,
                                        Qlm, Klm, A, S, Gm, Vmg, wv);

    // L5: BV partials
    bv_partial_kernel<<<dim3(8, NBH), 256>>>(S, V, BVp, csump);

    // L6: pinv apply (BV reduce + CBV)
    pinv_apply_kernel<<<NBH, 256, 50432>>>(Gm, Vmg, wv, BVp, csump, CBV);

    // L7: A_hat @ CBV
    av_kernel<<<dim3(T_SEQ/64, NBH), 256>>>(A, CBV, ah, al);

    // L8: out projection (3-term)
    dim3 go(DMODEL/128, NROWS/128);
    gemm3_kernel<<<go, 256, G3_SMEM>>>(ah, al,
                                       wh + 3*(size_t)DMODEL*DMODEL,
                                       wl + 3*(size_t)DMODEL*DMODEL, out,
                                       DMODEL, DMODEL);
}

// round 17
// speedup vs baseline: 1.2355x; 1.0715x over previous
#include <cuda_runtime.h>
#include <cuda_fp16.h>
#include <math.h>
#include <stdint.h>

// Problem constants: B=2, T=4096, d_model=1024, H=16, d_head=64, m=64
#define T_SEQ 4096
#define DMODEL 1024
#define NBH    32      // B*H
#define NROWS  8192    // B*T
#define NSWEEP 10

// ---------------- device scratch (no runtime allocation allowed) ----------------
__device__ __align__(16) float g_QKV[3 * NROWS * DMODEL];   // Q | K | V
__device__ __align__(16) float g_A[NBH * T_SEQ * 64];       // A_hat
__device__ __align__(16) float g_S[NBH * T_SEQ * 64];       // exp(B scores)
__device__ __align__(16) float g_xlm[128 * DMODEL];         // segment means of x
__device__ __align__(16) float g_Qlm[NBH * 64 * 64];
__device__ __align__(16) float g_Klm[NBH * 64 * 64];
__device__ __align__(16) float g_CBV[NBH * 64 * 64];
__device__ __align__(16) float g_BVpart[NBH * 8 * 64 * 64];
__device__ float g_csump[NBH * 8 * 64];
// Jacobi SVD intermediates (COLUMN-major: out[c*64+r] = M[r][c])
__device__ __align__(16) float g_Gm[NBH * 64 * 64];
__device__ __align__(16) float g_Vm[NBH * 64 * 64];
__device__ float g_wv[NBH * 64];
// QK-done counter for in-mega gating
__device__ unsigned int g_qkdone;
// fp16 splits
__device__ __align__(16) __half g_xh[NROWS * DMODEL];
__device__ __align__(16) __half g_xl[NROWS * DMODEL];
__device__ __align__(16) __half g_wh[4][DMODEL * DMODEL];
__device__ __align__(16) __half g_wl[4][DMODEL * DMODEL];
__device__ __align__(16) __half g_ah[NROWS * DMODEL];
__device__ __align__(16) __half g_al[NROWS * DMODEL];

// =====================  helpers  =====================
__device__ __forceinline__ uint32_t smem_u32(const void* p) {
    return (uint32_t)__cvta_generic_to_shared(p);
}
__device__ __forceinline__ void cp16(uint32_t dst, const void* src) {
    asm volatile("cp.async.cg.shared.global [%0], [%1], 16;" :: "r"(dst), "l"(src));
}
__device__ __forceinline__ void ldsm_x4(uint32_t* r, uint32_t addr) {
    asm volatile("ldmatrix.sync.aligned.m8n8.x4.shared.b16 {%0,%1,%2,%3}, [%4];"
        : "=r"(r[0]), "=r"(r[1]), "=r"(r[2]), "=r"(r[3]) : "r"(addr));
}
#define MMA16816F(d, a, b) \
    asm volatile("mma.sync.aligned.m16n8k16.row.col.f32.f16.f16.f32 " \
        "{%0,%1,%2,%3},{%4,%5,%6,%7},{%8,%9},{%0,%1,%2,%3};" \
        : "+f"((d)[0]), "+f"((d)[1]), "+f"((d)[2]), "+f"((d)[3]) \
        : "r"((a)[0]), "r"((a)[1]), "r"((a)[2]), "r"((a)[3]), \
          "r"((b)[0]), "r"((b)[1]))

// ---------------------------------------------------------------------------
// One flat split kernel: weights (hi+lo) then x (hi+lo). Also resets gate.
// ---------------------------------------------------------------------------
__device__ __forceinline__ void split4(float4 v, __half2* hi, __half2* lo, size_t i2) {
    __half h0 = __float2half(v.x), h1 = __float2half(v.y);
    __half h2 = __float2half(v.z), h3 = __float2half(v.w);
    __half2 H0, H1, L0, L1;
    H0.x = h0; H0.y = h1; H1.x = h2; H1.y = h3;
    L0.x = __float2half(v.x - __half2float(h0));
    L0.y = __float2half(v.y - __half2float(h1));
    L1.x = __float2half(v.z - __half2float(h2));
    L1.y = __float2half(v.w - __half2float(h3));
    hi[i2] = H0; hi[i2+1] = H1;
    lo[i2] = L0; lo[i2+1] = L1;
}

__global__ void split_all_kernel(
    const float4* __restrict__ x,
    const float4* __restrict__ W0, const float4* __restrict__ W1,
    const float4* __restrict__ W2, const float4* __restrict__ W3,
    __half2* __restrict__ xh2, __half2* __restrict__ xl2,
    __half2* __restrict__ wh2, __half2* __restrict__ wl2)
{
    int idx = blockIdx.x * 256 + threadIdx.x;
    if (idx == 0) g_qkdone = 0u;            // reset gate each replay
    if (idx < 4 * 262144) {
        int w = idx >> 18;
        int i = idx & 262143;
        const float4* src = (w == 0) ? W0 : (w == 1) ? W1 : (w == 2) ? W2 : W3;
        split4(src[i], wh2, wl2, (size_t)w * 524288 + 2 * (size_t)i);
    } else {
        int j = idx - 4 * 262144;
        split4(x[j], xh2, xl2, 2 * (size_t)j);
    }
}

// ---------------------------------------------------------------------------
// xlm: segment means of x.  grid 128, 256 threads.
// ---------------------------------------------------------------------------
__global__ void xlm_kernel(const float* __restrict__ x, float* __restrict__ xlm)
{
    int m = blockIdx.x;            // 0..127
    int b = m >> 6, seg = m & 63;
    const float* base = x + ((size_t)b * T_SEQ + seg * 64) * DMODEL;
    int tid = threadIdx.x;
#pragma unroll
    for (int cc = 0; cc < 4; cc++) {
        int c = tid + cc * 256;
        float s = 0.f;
#pragma unroll 8
        for (int r = 0; r < 64; r++) s += base[(size_t)r * DMODEL + c];
        xlm[(size_t)m * DMODEL + c] = s * 0.015625f;
    }
}

// ---------------------------------------------------------------------------
// lmgemm: Qlm/Klm = xlm @ W^T  (fp32 SIMT, exact — feeds the pinv path).
// ---------------------------------------------------------------------------
__global__ __launch_bounds__(256) void lmgemm_kernel(
    const float* __restrict__ xlm,
    const float* __restrict__ Wq, const float* __restrict__ Wk,
    float* __restrict__ Qlm, float* __restrict__ Klm)
{
    const float* W = blockIdx.y ? Wk : Wq;
    float* out = blockIdx.y ? Klm : Qlm;
    int n0 = blockIdx.x * 64;
    __shared__ float xs[16][132];   // [k][m]
    __shared__ float ws[16][68];    // [k][n]
    int tid = threadIdx.x;
    int ti = tid >> 3;   // 0..31
    int tj = tid & 7;    // 0..7
    float acc[4][8] = {};
    for (int k0 = 0; k0 < DMODEL; k0 += 16) {
        __syncthreads();
        for (int i = tid; i < 512; i += 256) {
            int m = i >> 2, kq = i & 3;
            float4 v = *(const float4*)&xlm[(size_t)m * DMODEL + k0 + kq*4];
            xs[kq*4+0][m] = v.x; xs[kq*4+1][m] = v.y;
            xs[kq*4+2][m] = v.z; xs[kq*4+3][m] = v.w;
        }
        if (tid < 256) {
            int i = tid;
            if (i < 256) {
                int n = i >> 2, kq = i & 3;
                float4 v = *(const float4*)&W[(size_t)(n0 + n) * DMODEL + k0 + kq*4];
                ws[kq*4+0][n] = v.x; ws[kq*4+1][n] = v.y;
                ws[kq*4+2][n] = v.z; ws[kq*4+3][n] = v.w;
            }
        }
        __syncthreads();
#pragma unroll
        for (int kk = 0; kk < 16; kk++) {
            float a[4], b[8];
#pragma unroll
            for (int x2 = 0; x2 < 4; x2++) a[x2] = xs[kk][ti*4 + x2];
#pragma unroll
            for (int y = 0; y < 8; y++) b[y] = ws[kk][tj*8 + y];
#pragma unroll
            for (int x2 = 0; x2 < 4; x2++)
#pragma unroll
                for (int y = 0; y < 8; y++)
                    acc[x2][y] = fmaf(a[x2], b[y], acc[x2][y]);
        }
    }
#pragma unroll
    for (int x2 = 0; x2 < 4; x2++) {
        int m = ti*4 + x2;
        int b = m >> 6, mi = m & 63;
#pragma unroll
        for (int y = 0; y < 8; y++) {
            int n = n0 + tj*8 + y;
            int h = n >> 6, d = n & 63;
            out[((size_t)(b*16 + h) * 64 + mi) * 64 + d] = acc[x2][y];
        }
    }
}

// ---------------------------------------------------------------------------
// 3-term NT GEMM tile body: C = Ah*Bh + Ah*Bl + Al*Bh (fp32 acc).
// ---------------------------------------------------------------------------
#define GM_ROWB  80
#define GM_TILE  (128 * GM_ROWB)      // 10240
#define G3_STAGE (4 * GM_TILE)        // 40960
#define G3_SMEM  (2 * G3_STAGE)       // 81920

__device__ void dev_gemm3(char* smem, int m0, int n0,
    const __half* __restrict__ Ahi, const __half* __restrict__ Alo,
    const __half* __restrict__ Bhi, const __half* __restrict__ Blo,
    float* __restrict__ C, int N, int K)
{
    const uint32_t sb = smem_u32(smem);
    const int tid = threadIdx.x;
    const int wid = tid >> 5, lane = tid & 31;
    const int wr = (wid & 3) * 32;
    const int wc = (wid >> 2) * 64;
    const int lrow = tid >> 2;
    const int lseg = tid & 3;

    const int nchunks = K >> 5;

    auto load_stage = [&](int s, int kc) {
        uint32_t st = sb + s * G3_STAGE;
#pragma unroll
        for (int i = 0; i < 2; i++) {
            int row = lrow + i * 64;
            uint32_t off = row * GM_ROWB + lseg * 16;
            cp16(st +             off, Ahi + (size_t)(m0 + row) * K + kc + lseg * 8);
            cp16(st + GM_TILE   + off, Alo + (size_t)(m0 + row) * K + kc + lseg * 8);
            cp16(st + 2*GM_TILE + off, Bhi + (size_t)(n0 + row) * K + kc + lseg * 8);
            cp16(st + 3*GM_TILE + off, Blo + (size_t)(n0 + row) * K + kc + lseg * 8);
        }
        asm volatile("cp.async.commit_group;" ::: "memory");
    };

    load_stage(0, 0);
    load_stage(1, 32);

    float accF[2][8][4];
#pragma unroll
    for (int mt = 0; mt < 2; mt++)
#pragma unroll
        for (int nt = 0; nt < 8; nt++)
#pragma unroll
            for (int q = 0; q < 4; q++) accF[mt][nt][q] = 0.f;

    const uint32_t aBase = (uint32_t)(wr + (lane & 15)) * GM_ROWB + (uint32_t)(lane >> 4) * 16;
    const uint32_t bBase = (uint32_t)(wc + (lane & 7) + ((lane >> 4) * 8)) * GM_ROWB
                         + (uint32_t)((lane >> 3) & 1) * 16;

    const int fr = lane >> 2;
    const int fc = (lane & 3) * 2;

    for (int c = 0; c < nchunks; c++) {
        int s = c & 1;
        asm volatile("cp.async.wait_group 1;" ::: "memory");
        __syncthreads();
        uint32_t st  = sb + s * G3_STAGE;
        uint32_t tAH = st;
        uint32_t tAL = st + GM_TILE;
        uint32_t tBH = st + 2*GM_TILE;
        uint32_t tBL = st + 3*GM_TILE;

#pragma unroll
        for (int k16 = 0; k16 < 2; k16++) {
            uint32_t kb = k16 * 32;
            uint32_t aH[2][4], aL[2][4];
#pragma unroll
            for (int mt = 0; mt < 2; mt++) {
                uint32_t ao = aBase + mt * 16 * GM_ROWB + kb;
                ldsm_x4(aH[mt], tAH + ao);
                ldsm_x4(aL[mt], tAL + ao);
            }
            uint32_t bH[8][2], bL[8][2];
#pragma unroll
            for (int p = 0; p < 4; p++) {
                uint32_t bo = bBase + p * 16 * GM_ROWB + kb;
                uint32_t tH[4], tL[4];
                ldsm_x4(tH, tBH + bo);
                ldsm_x4(tL, tBL + bo);
                bH[2*p][0] = tH[0]; bH[2*p][1] = tH[1];
                bH[2*p+1][0] = tH[2]; bH[2*p+1][1] = tH[3];
                bL[2*p][0] = tL[0]; bL[2*p][1] = tL[1];
                bL[2*p+1][0] = tL[2]; bL[2*p+1][1] = tL[3];
            }
#pragma unroll
            for (int mt = 0; mt < 2; mt++)
#pragma unroll
                for (int nt = 0; nt < 8; nt++)
                    MMA16816F(accF[mt][nt], aH[mt], bH[nt]);
#pragma unroll
            for (int mt = 0; mt < 2; mt++)
#pragma unroll
                for (int nt = 0; nt < 8; nt++)
                    MMA16816F(accF[mt][nt], aH[mt], bL[nt]);
#pragma unroll
            for (int mt = 0; mt < 2; mt++)
#pragma unroll
                for (int nt = 0; nt < 8; nt++)
                    MMA16816F(accF[mt][nt], aL[mt], bH[nt]);
        }
        __syncthreads();
        if (c + 2 < nchunks) {
            load_stage(s, (c + 2) * 32);
        } else {
            asm volatile("cp.async.commit_group;" ::: "memory");
        }
    }

#pragma unroll
    for (int mt = 0; mt < 2; mt++) {
#pragma unroll
        for (int nt = 0; nt < 8; nt++) {
            int row = m0 + wr + mt*16 + fr;
            int col = n0 + wc + nt*8 + fc;
            *(float2*)(C + (size_t)row * N + col) =
                make_float2(accF[mt][nt][0], accF[mt][nt][1]);
            *(float2*)(C + (size_t)(row + 8) * N + col) =
                make_float2(accF[mt][nt][2], accF[mt][nt][3]);
        }
    }
}

// standalone gemm3 kernel (out projection)
__global__ __launch_bounds__(256, 2) void gemm3_kernel(
    const __half* __restrict__ Ahi, const __half* __restrict__ Alo,
    const __half* __restrict__ Bhi, const __half* __restrict__ Blo,
    float* __restrict__ C, int N, int K)
{
    extern __shared__ __align__(128) char smem[];
    dev_gemm3(smem, blockIdx.y * 128, blockIdx.x * 128,
              Ahi, Alo, Bhi, Blo, C, N, K);
}

// ---------------------------------------------------------------------------
// Jacobi SVD body. Column-major pitch-68, float4 ops, tracked norms,
// fast-math on angle path only; sigma/cutoff/softmax exact.
// ---------------------------------------------------------------------------
#define JP 68

__device__ void dev_jacobi(char* smemc, int bh,
    const float* __restrict__ Qlm, const float* __restrict__ Klm,
    float* __restrict__ Gout, float* __restrict__ Vout, float* __restrict__ wv)
{
    float* sp = (float*)smemc;
    float* Gt   = sp;             // 64*68
    float* Vt   = sp + 4352;      // 64*68
    float* cn   = sp + 8704;      // 64
    float* svec = sp + 8768;      // 64
    int tid = threadIdx.x;
    int ti = tid >> 4, tj = tid & 15;

    for (int i = tid; i < 4096; i += 256) {
        int r = i >> 6, c = i & 63;
        Gt[r*JP + c] = Qlm[(size_t)bh*4096 + i];
        Vt[r*JP + c] = Klm[(size_t)bh*4096 + i];
    }
    __syncthreads();

    float cacc[4][4] = {};
    for (int d = 0; d < 64; d++) {
        float qa[4], kb[4];
#pragma unroll
        for (int x = 0; x < 4; x++) qa[x] = Gt[(ti*4+x)*JP + d];
#pragma unroll
        for (int y = 0; y < 4; y++) kb[y] = Vt[(tj*4+y)*JP + d];
#pragma unroll
        for (int x = 0; x < 4; x++)
#pragma unroll
            for (int y = 0; y < 4; y++)
                cacc[x][y] = fmaf(qa[x], kb[y], cacc[x][y]);
    }
    __syncthreads();
#pragma unroll
    for (int x = 0; x < 4; x++)
#pragma unroll
        for (int y = 0; y < 4; y++)
            Vt[(ti*4+x)*JP + tj*4+y] = cacc[x][y] * 0.125f;
    __syncthreads();

    // row softmax (exact)
    if (tid < 64) {
        float mx = -INFINITY;
        for (int c = 0; c < 64; c++) mx = fmaxf(mx, Vt[tid*JP + c]);
        float z = 0.f;
        for (int c = 0; c < 64; c++) {
            float e = expf(Vt[tid*JP + c] - mx);
            Vt[tid*JP + c] = e; z += e;
        }
        float inv = 1.f / z;
        for (int c = 0; c < 64; c++) Vt[tid*JP + c] *= inv;
    }
    __syncthreads();

    for (int i = tid; i < 4096; i += 256) {
        int r = i >> 6, c = i & 63;
        Gt[c*JP + r] = Vt[r*JP + c];
    }
    __syncthreads();
    for (int i = tid; i < 4096; i += 256) {
        int r = i >> 6, c = i & 63;
        Vt[c*JP + r] = (r == c) ? 1.f : 0.f;
    }
    __syncthreads();

    {
        int p = tid >> 3, lane = tid & 7;
        for (int sw = 0; sw < NSWEEP; sw++) {
            if (tid < 64) {
                const float* col = Gt + tid*JP;
                float s = 0.f;
#pragma unroll
                for (int k4 = 0; k4 < 16; k4++) {
                    float4 v = *(const float4*)(col + 4*k4);
                    s = fmaf(v.x, v.x, s); s = fmaf(v.y, v.y, s);
                    s = fmaf(v.z, v.z, s); s = fmaf(v.w, v.w, s);
                }
                cn[tid] = s;
            }
            __syncthreads();

            for (int r = 0; r < 63; r++) {
                int ci, cj;
                if (p == 0) { ci = 63; cj = r; }
                else { ci = (r + p) % 63; cj = (r - p + 63) % 63; }
                float* gi = Gt + ci*JP + 8*lane;
                float* gj = Gt + cj*JP + 8*lane;
                float4 a0 = *(float4*)(gi);
                float4 a1 = *(float4*)(gi + 4);
                float4 b0 = *(float4*)(gj);
                float4 b1 = *(float4*)(gj + 4);
                float gg = a0.x*b0.x + a0.y*b0.y + a0.z*b0.z + a0.w*b0.w
                         + a1.x*b1.x + a1.y*b1.y + a1.z*b1.z + a1.w*b1.w;
#pragma unroll
                for (int o = 4; o > 0; o >>= 1)
                    gg += __shfl_xor_sync(0xffffffffu, gg, o);
                float aa = cn[ci], bb = cn[cj];
                float c_ = 1.f, s_ = 0.f;
                if (fabsf(gg) > 1e-30f) {
                    float zeta = __fdividef(bb - aa, 2.0f * gg);
                    float t = copysignf(
                        __fdividef(1.0f, fabsf(zeta) + sqrtf(fmaf(zeta, zeta, 1.0f))),
                        zeta);
                    c_ = rsqrtf(fmaf(t, t, 1.0f));
                    s_ = c_ * t;
                }
                if (s_ != 0.f) {
                    float4 n0, n1, m0, m1;
                    n0.x = c_*a0.x - s_*b0.x; n0.y = c_*a0.y - s_*b0.y;
                    n0.z = c_*a0.z - s_*b0.z; n0.w = c_*a0.w - s_*b0.w;
                    n1.x = c_*a1.x - s_*b1.x; n1.y = c_*a1.y - s_*b1.y;
                    n1.z = c_*a1.z - s_*b1.z; n1.w = c_*a1.w - s_*b1.w;
                    m0.x = s_*a0.x + c_*b0.x; m0.y = s_*a0.y + c_*b0.y;
                    m0.z = s_*a0.z + c_*b0.z; m0.w = s_*a0.w + c_*b0.w;
                    m1.x = s_*a1.x + c_*b1.x; m1.y = s_*a1.y + c_*b1.y;
                    m1.z = s_*a1.z + c_*b1.z; m1.w = s_*a1.w + c_*b1.w;
                    *(float4*)(gi)     = n0; *(float4*)(gi + 4) = n1;
                    *(float4*)(gj)     = m0; *(float4*)(gj + 4) = m1;
                    float* vi = Vt + ci*JP + 8*lane;
                    float* vj = Vt + cj*JP + 8*lane;
                    float4 p0 = *(float4*)(vi), p1 = *(float4*)(vi + 4);
                    float4 q0 = *(float4*)(vj), q1 = *(float4*)(vj + 4);
                    float4 u0, u1, w0, w1;
                    u0.x = c_*p0.x - s_*q0.x; u0.y = c_*p0.y - s_*q0.y;
                    u0.z = c_*p0.z - s_*q0.z; u0.w = c_*p0.w - s_*q0.w;
                    u1.x = c_*p1.x - s_*q1.x; u1.y = c_*p1.y - s_*q1.y;
                    u1.z = c_*p1.z - s_*q1.z; u1.w = c_*p1.w - s_*q1.w;
                    w0.x = s_*p0.x + c_*q0.x; w0.y = s_*p0.y + c_*q0.y;
                    w0.z = s_*p0.z + c_*q0.z; w0.w = s_*p0.w + c_*q0.w;
                    w1.x = s_*p1.x + c_*q1.x; w1.y = s_*p1.y + c_*q1.y;
                    w1.z = s_*p1.z + c_*q1.z; w1.w = s_*p1.w + c_*q1.w;
                    *(float4*)(vi)     = u0; *(float4*)(vi + 4) = u1;
                    *(float4*)(vj)     = w0; *(float4*)(vj + 4) = w1;
                    if (lane == 0) {
                        float cc = c_*c_, ss2 = s_*s_, cs2 = 2.f*c_*s_;
                        cn[ci] = cc*aa - cs2*gg + ss2*bb;
                        cn[cj] = ss2*aa + cs2*gg + cc*bb;
                    }
                }
                __syncthreads();
            }
        }
    }

    // exact sigma + cutoff
    if (tid < 64) {
        const float* col = Gt + tid*JP;
        float s = 0.f;
#pragma unroll
        for (int k4 = 0; k4 < 16; k4++) {
            float4 v = *(const float4*)(col + 4*k4);
            s = fmaf(v.x, v.x, s); s = fmaf(v.y, v.y, s);
            s = fmaf(v.z, v.z, s); s = fmaf(v.w, v.w, s);
        }
        svec[tid] = sqrtf(s);
    }
    __syncthreads();
    if (tid < 64) {
        float smax = 0.f;
        for (int c = 0; c < 64; c++) smax = fmaxf(smax, svec[c]);
        float cut = 7.62939453125e-5f * smax;
        float s = svec[tid];
        wv[bh*64 + tid] = (s > cut) ? 1.0f / (s * s) : 0.0f;
    }
    for (int i = tid; i < 4096; i += 256) {
        int c = i >> 6, r = i & 63;
        Gout[(size_t)bh*4096 + i] = Gt[c*JP + r];
        Vout[(size_t)bh*4096 + i] = Vt[c*JP + r];
    }
}

// ---------------------------------------------------------------------------
// scores body (256 threads, 256 t per CTA).
// ---------------------------------------------------------------------------
__device__ void dev_scores(char* smemc, int idx,
    const float* __restrict__ Q, const float* __restrict__ K,
    const float* __restrict__ Klm, const float* __restrict__ Qlm,
    float* __restrict__ A, float* __restrict__ S)
{
    int zz  = idx >> 9;
    int rem = idx & 511;
    int bh  = rem >> 4;
    int tch = rem & 15;
    const float* X   = zz ? K : Q;
    const float* Ylm = zz ? Qlm : Klm;
    float* out = zz ? S : A;
    int b = bh >> 4, h = bh & 15;
    int tid = threadIdx.x;
    int t = tch * 256 + tid;

    float4* Ks = (float4*)smemc;
    float* Ssc = (float*)(smemc + 16384);

    const float4* Ysrc = (const float4*)(Ylm + (size_t)bh * 4096);
    for (int i = tid; i < 1024; i += 256) Ks[i] = Ysrc[i];
    __syncthreads();

    const float4* xrow = (const float4*)(X + ((size_t)b * T_SEQ + t) * DMODEL + h * 64);
    float q[64];
#pragma unroll
    for (int d4 = 0; d4 < 16; d4++) {
        float4 v = xrow[d4];
        q[4*d4+0]=v.x; q[4*d4+1]=v.y; q[4*d4+2]=v.z; q[4*d4+3]=v.w;
    }
    for (int mi = 0; mi < 64; mi++) {
        float acc = 0.f;
#pragma unroll
        for (int d4 = 0; d4 < 16; d4++) {
            float4 k4 = Ks[mi*16 + d4];
            acc = fmaf(q[4*d4+0], k4.x, acc);
            acc = fmaf(q[4*d4+1], k4.y, acc);
            acc = fmaf(q[4*d4+2], k4.z, acc);
            acc = fmaf(q[4*d4+3], k4.w, acc);
        }
        Ssc[mi*256 + tid] = acc * 0.125f;
    }
    float* orow = out + ((size_t)bh * T_SEQ + t) * 64;
    if (zz == 0) {
        float m = -INFINITY;
        for (int mi = 0; mi < 64; mi++) m = fmaxf(m, Ssc[mi*256 + tid]);
        float z = 0.f;
        for (int mi = 0; mi < 64; mi++) {
            float e = expf(Ssc[mi*256 + tid] - m);
            Ssc[mi*256 + tid] = e; z += e;
        }
        float inv = 1.0f / z;
        for (int mi = 0; mi < 64; mi += 4) {
            float4 o = make_float4(Ssc[(mi+0)*256+tid]*inv, Ssc[(mi+1)*256+tid]*inv,
                                   Ssc[(mi+2)*256+tid]*inv, Ssc[(mi+3)*256+tid]*inv);
            *(float4*)(orow + mi) = o;
        }
    } else {
        for (int mi = 0; mi < 64; mi += 4) {
            float4 o = make_float4(expf(Ssc[(mi+0)*256+tid]), expf(Ssc[(mi+1)*256+tid]),
                                   expf(Ssc[(mi+2)*256+tid]), expf(Ssc[(mi+3)*256+tid]));
            *(float4*)(orow + mi) = o;
        }
    }
}

// ---------------------------------------------------------------------------
// MEGA kernel:
//  [0,32)      jacobi
//  [32,1056)   Q,K projection tiles (signal g_qkdone after stores)
//  [1056,1568) V projection tiles
//  [1568,2592) scores (gated on all 1024 QK tiles; deadlock-free since
//              waiters only depend on lower-indexed CTAs)
// ---------------------------------------------------------------------------
__global__ __launch_bounds__(256, 2) void mega_kernel(
    const __half* __restrict__ xh, const __half* __restrict__ xl,
    const __half* __restrict__ wh, const __half* __restrict__ wl,
    float* __restrict__ QKV,
    const float* __restrict__ Qlm, const float* __restrict__ Klm,
    float* __restrict__ A, float* __restrict__ S,
    float* __restrict__ Gout, float* __restrict__ Vout, float* __restrict__ wv)
{
    extern __shared__ __align__(128) char smem[];
    int bx = blockIdx.x;
    const float* Q = QKV;
    const float* K = QKV + (size_t)NROWS * DMODEL;
    if (bx < 32) {
        dev_jacobi(smem, bx, Qlm, Klm, Gout, Vout, wv);
    } else if (bx < 1056) {
        int idx = bx - 32;             // 0..1023
        int z = idx >> 9;              // 0,1 -> Wq,Wk
        int rem = idx & 511;
        dev_gemm3(smem, (rem >> 3) * 128, (rem & 7) * 128,
                  xh, xl,
                  wh + (size_t)z * DMODEL * DMODEL,
                  wl + (size_t)z * DMODEL * DMODEL,
                  QKV + (size_t)z * NROWS * DMODEL, DMODEL, DMODEL);
        __threadfence();
        __syncthreads();
        if (threadIdx.x == 0) atomicAdd(&g_qkdone, 1u);
    } else if (bx < 1568) {
        int rem = bx - 1056;           // 0..511
        dev_gemm3(smem, (rem >> 3) * 128, (rem & 7) * 128,
                  xh, xl,
                  wh + 2*(size_t)DMODEL * DMODEL,
                  wl + 2*(size_t)DMODEL * DMODEL,
                  QKV + 2*(size_t)NROWS * DMODEL, DMODEL, DMODEL);
    } else {
        if (threadIdx.x == 0) {
            while (atomicAdd(&g_qkdone, 0u) < 1024u) __nanosleep(256);
        }
        __syncthreads();
        __threadfence();
        dev_scores(smem, bx - 1568, Q, K, Klm, Qlm, A, S);
    }
}

// ---------------------------------------------------------------------------
// BV partials over 512-row chunks: part = E^T V + per-column sums of E.
// ---------------------------------------------------------------------------
__global__ __launch_bounds__(256) void bv_partial_kernel(
    const float* __restrict__ Se, const float* __restrict__ V,
    float* __restrict__ part, float* __restrict__ csump)
{
    int chunk = blockIdx.x, bh = blockIdx.y;
    int b = bh >> 4, h = bh & 15;
    __shared__ float Es[64][65];
    __shared__ float Vs[64][65];
    __shared__ float sred[256];
    int tid = threadIdx.x;
    int ti = tid >> 4, tj = tid & 15;
    float acc[4][4] = {};
    float cs = 0.f;
    for (int t0 = chunk*512; t0 < chunk*512 + 512; t0 += 64) {
        __syncthreads();
        for (int i = tid; i < 4096; i += 256) {
            int r = i >> 6, c = i & 63;
            float e = Se[((size_t)bh*T_SEQ + t0 + r)*64 + c];
            Es[r][c] = e;
            cs += e;
            Vs[r][c] = V[((size_t)b*T_SEQ + t0 + r)*DMODEL + h*64 + c];
        }
        __syncthreads();
#pragma unroll 4
        for (int r = 0; r < 64; r++) {
            float a[4], bb[4];
#pragma unroll
            for (int x = 0; x < 4; x++) a[x]  = Es[r][ti*4+x];
#pragma unroll
            for (int y = 0; y < 4; y++) bb[y] = Vs[r][tj*4+y];
#pragma unroll
            for (int x = 0; x < 4; x++)
#pragma unroll
                for (int y = 0; y < 4; y++)
                    acc[x][y] = fmaf(a[x], bb[y], acc[x][y]);
        }
    }
    float* dst = part + ((size_t)(bh*8 + chunk)) * 4096;
#pragma unroll
    for (int x = 0; x < 4; x++)
#pragma unroll
        for (int y = 0; y < 4; y++)
            dst[(ti*4+x)*64 + tj*4+y] = acc[x][y];
    sred[tid] = cs;
    __syncthreads();
    if (tid < 64)
        csump[(size_t)(bh*8 + chunk)*64 + tid] =
            sred[tid] + sred[tid+64] + sred[tid+128] + sred[tid+192];
}

// ---------------------------------------------------------------------------
// pinv apply: BV = (sum partials)/colsum;  CBV = V * diag(w) * G^T * BV.
// ---------------------------------------------------------------------------
__global__ __launch_bounds__(256) void pinv_apply_kernel(
    const float* __restrict__ Gin, const float* __restrict__ Vin,
    const float* __restrict__ wv,
    const float* __restrict__ BVp, const float* __restrict__ csump,
    float* __restrict__ CBV)
{
    extern __shared__ float sp[];
    float* Gs   = sp;
    float* Vs   = sp + 4160;
    float* W    = sp + 8320;
    float* wvec = sp + 12480;
    float* dvec = sp + 12544;
    int bh = blockIdx.x;
    int tid = threadIdx.x;
    int ti = tid >> 4, tj = tid & 15;

    for (int i = tid; i < 4096; i += 256) {
        int c = i >> 6, q = i & 63;
        Gs[c*65 + q] = Gin[(size_t)bh*4096 + i];
        Vs[c*65 + q] = Vin[(size_t)bh*4096 + i];
    }
    if (tid < 64) {
        wvec[tid] = wv[bh*64 + tid];
        float den = 0.f;
#pragma unroll
        for (int ch = 0; ch < 8; ch++) den += csump[(size_t)(bh*8 + ch)*64 + tid];
        dvec[tid] = 1.0f / den;
    }
    __syncthreads();

    for (int i = tid; i < 4096; i += 256) {
        float s = 0.f;
#pragma unroll
        for (int ch = 0; ch < 8; ch++) s += BVp[((size_t)(bh*8 + ch))*4096 + i];
        W[(i >> 6)*65 + (i & 63)] = s * dvec[i >> 6];
    }
    __syncthreads();

    float t1[4][4] = {};
    for (int q = 0; q < 64; q++) {
        float a[4], bb[4];
#pragma unroll
        for (int x = 0; x < 4; x++) a[x]  = Gs[(ti*4+x)*65 + q];
#pragma unroll
        for (int y = 0; y < 4; y++) bb[y] = W[q*65 + tj*4+y];
#pragma unroll
        for (int x = 0; x < 4; x++)
#pragma unroll
            for (int y = 0; y < 4; y++)
                t1[x][y] = fmaf(a[x], bb[y], t1[x][y]);
    }
#pragma unroll
    for (int x = 0; x < 4; x++) {
        float w = wvec[ti*4+x];
#pragma unroll
        for (int y = 0; y < 4; y++) t1[x][y] *= w;
    }
    __syncthreads();
#pragma unroll
    for (int x = 0; x < 4; x++)
#pragma unroll
        for (int y = 0; y < 4; y++)
            Gs[(ti*4+x)*65 + tj*4+y] = t1[x][y];
    __syncthreads();

    float cb[4][4] = {};
    for (int q = 0; q < 64; q++) {
        float a[4], bb[4];
#pragma unroll
        for (int x = 0; x < 4; x++) a[x]  = Vs[q*65 + ti*4+x];
#pragma unroll
        for (int y = 0; y < 4; y++) bb[y] = Gs[q*65 + tj*4+y];
#pragma unroll
        for (int x = 0; x < 4; x++)
#pragma unroll
            for (int y = 0; y < 4; y++)
                cb[x][y] = fmaf(a[x], bb[y], cb[x][y]);
    }
#pragma unroll
    for (int x = 0; x < 4; x++)
#pragma unroll
        for (int y = 0; y < 4; y++)
            CBV[(size_t)bh*4096 + (ti*4+x)*64 + tj*4+y] = cb[x][y];
}

// ---------------------------------------------------------------------------
// Y = A_hat @ CBV per head -> fp16 hi + lo (merged-head layout).
// ---------------------------------------------------------------------------
__global__ __launch_bounds__(256) void av_kernel(
    const float* __restrict__ Ahat, const float* __restrict__ CBV,
    __half* __restrict__ ahp, __half* __restrict__ alp)
{
    int bh = blockIdx.y;
    int b = bh >> 4, hh = bh & 15;
    int t0 = blockIdx.x * 64;
    __shared__ float As[64*65];
    __shared__ float Cs[64*65];
    int tid = threadIdx.x;
    for (int i = tid; i < 4096; i += 256) {
        int tl = i >> 6, c = i & 63;
        As[c*65 + tl] = Ahat[((size_t)bh*T_SEQ + t0 + tl)*64 + c];
        Cs[tl*65 + c] = CBV[(size_t)bh*4096 + i];
    }
    __syncthreads();
    int ti = tid >> 4, tj = tid & 15;
    float acc[4][4] = {};
    for (int c = 0; c < 64; c++) {
        float a[4], bb[4];
#pragma unroll
        for (int x = 0; x < 4; x++) a[x]  = As[c*65 + ti*4+x];
#pragma unroll
        for (int y = 0; y < 4; y++) bb[y] = Cs[c*65 + tj*4+y];
#pragma unroll
        for (int x = 0; x < 4; x++)
#pragma unroll
            for (int y = 0; y < 4; y++)
                acc[x][y] = fmaf(a[x], bb[y], acc[x][y]);
    }
#pragma unroll
    for (int x = 0; x < 4; x++) {
        size_t idx = ((size_t)b*T_SEQ + t0 + ti*4 + x)*DMODEL + hh*64 + tj*4;
#pragma unroll
        for (int y = 0; y < 4; y += 2) {
            float v0 = acc[x][y], v1 = acc[x][y+1];
            __half h0 = __float2half(v0);
            __half h1 = __float2half(v1);
            __half2 Hp, Lp;
            Hp.x = h0; Hp.y = h1;
            Lp.x = __float2half(v0 - __half2float(h0));
            Lp.y = __float2half(v1 - __half2float(h1));
            *(__half2*)(ahp + idx + y) = Hp;
            *(__half2*)(alp + idx + y) = Lp;
        }
    }
}

// ---------------------------------------------------------------------------
extern "C" void kernel_launch(void* const* d_in, const int* in_sizes, int n_in,
                              void* d_out, int out_size)
{
    (void)in_sizes; (void)n_in; (void)out_size;
    const float* x = (const float*)d_in[0];
    const float* Wq = (const float*)d_in[1];
    const float* Wk = (const float*)d_in[2];
    const float* Wv = (const float*)d_in[3];
    const float* Wo = (const float*)d_in[4];
    float* out = (float*)d_out;

    float *QKV, *A, *S, *xlm, *Qlm, *Klm, *CBV, *BVp, *csump, *Gm, *Vmg, *wv;
    __half *xh, *xl, *wh, *wl, *ah, *al;
    cudaGetSymbolAddress((void**)&QKV,   g_QKV);
    cudaGetSymbolAddress((void**)&A,     g_A);
    cudaGetSymbolAddress((void**)&S,     g_S);
    cudaGetSymbolAddress((void**)&xlm,   g_xlm);
    cudaGetSymbolAddress((void**)&Qlm,   g_Qlm);
    cudaGetSymbolAddress((void**)&Klm,   g_Klm);
    cudaGetSymbolAddress((void**)&CBV,   g_CBV);
    cudaGetSymbolAddress((void**)&BVp,   g_BVpart);
    cudaGetSymbolAddress((void**)&csump, g_csump);
    cudaGetSymbolAddress((void**)&Gm,    g_Gm);
    cudaGetSymbolAddress((void**)&Vmg,   g_Vm);
    cudaGetSymbolAddress((void**)&wv,    g_wv);
    cudaGetSymbolAddress((void**)&xh,    g_xh);
    cudaGetSymbolAddress((void**)&xl,    g_xl);
    cudaGetSymbolAddress((void**)&wh,    g_wh);
    cudaGetSymbolAddress((void**)&wl,    g_wl);
    cudaGetSymbolAddress((void**)&ah,    g_ah);
    cudaGetSymbolAddress((void**)&al,    g_al);

    float* V = QKV + 2 * (size_t)NROWS * DMODEL;

    cudaFuncSetAttribute(gemm3_kernel,
                         cudaFuncAttributeMaxDynamicSharedMemorySize, G3_SMEM);
    cudaFuncSetAttribute(mega_kernel,
                         cudaFuncAttributeMaxDynamicSharedMemorySize, G3_SMEM);
    cudaFuncSetAttribute(pinv_apply_kernel,
                         cudaFuncAttributeMaxDynamicSharedMemorySize, 50432);

    // L1: all splits (+ gate reset)
    split_all_kernel<<<12288, 256>>>((const float4*)x,
        (const float4*)Wq, (const float4*)Wk, (const float4*)Wv, (const float4*)Wo,
        (__half2*)xh, (__half2*)xl, (__half2*)wh, (__half2*)wl);

    // L2: segment means of x (exact fp32)
    xlm_kernel<<<128, 256>>>(x, xlm);

    // L3: landmark projections Qlm/Klm = xlm @ W^T (exact fp32)
    lmgemm_kernel<<<dim3(16, 2), 256>>>(xlm, Wq, Wk, Qlm, Klm);

    // L4: MEGA = jacobi | QK | V | gated scores     <-- profiled slot
    mega_kernel<<<2592, 256, G3_SMEM>>>(xh, xl, wh, wl, QKV,
                                        Qlm, Klm, A, S, Gm, Vmg, wv);

    // L5: BV partials
    bv_partial_kernel<<<dim3(8, NBH), 256>>>(S, V, BVp, csump);

    // L6: pinv apply (BV reduce + CBV)
    pinv_apply_kernel<<<NBH, 256, 50432>>>(Gm, Vmg, wv, BVp, csump, CBV);

    // L7: A_hat @ CBV
    av_kernel<<<dim3(T_SEQ/64, NBH), 256>>>(A, CBV, ah, al);

    // L8: out projection (3-term)
    dim3 go(DMODEL/128, NROWS/128);
    gemm3_kernel<<<go, 256, G3_SMEM>>>(ah, al,
                                       wh + 3*(size_t)DMODEL*DMODEL,
                                       wl + 3*(size_t)DMODEL*DMODEL, out,
                                       DMODEL, DMODEL);
}